// round 7
// baseline (speedup 1.0000x reference)
#include <cuda_runtime.h>
#include <stdint.h>

#define B_  2
#define M_  2048
#define N_  2048
#define D_  1024
#define NH_ 16
#define DH_ 64

// Scratch (device globals: no allocation allowed)
// g_Q holds tf32-rounded (Q*scale*log2e) bits; g_K/g_V hold tf32-rounded bits.
__device__ float g_Q[(size_t)B_ * M_ * D_];
__device__ float g_K[(size_t)B_ * N_ * D_];
__device__ float g_V[(size_t)B_ * N_ * D_];
__device__ float g_C[(size_t)B_ * M_ * D_];
__device__ unsigned char g_mask[B_ * N_];

// ---------------------------------------------------------------------------
// helpers
// ---------------------------------------------------------------------------
__device__ __forceinline__ unsigned f2tf(float x) {
    unsigned u; asm("cvt.rna.tf32.f32 %0, %1;" : "=r"(u) : "f"(x)); return u;
}
__device__ __forceinline__ float ex2(float x) {
    float y; asm("ex2.approx.f32 %0, %1;" : "=f"(y) : "f"(x)); return y;
}
__device__ __forceinline__ void mma8(float* c, unsigned a0, unsigned a1, unsigned a2, unsigned a3,
                                     unsigned b0, unsigned b1) {
    asm volatile(
        "mma.sync.aligned.m16n8k8.row.col.f32.tf32.tf32.f32 "
        "{%0,%1,%2,%3},{%4,%5,%6,%7},{%8,%9},{%0,%1,%2,%3};\n"
        : "+f"(c[0]), "+f"(c[1]), "+f"(c[2]), "+f"(c[3])
        : "r"(a0), "r"(a1), "r"(a2), "r"(a3), "r"(b0), "r"(b1));
}
__device__ __forceinline__ void cpasync16(void* dst, const void* src) {
    unsigned d = (unsigned)__cvta_generic_to_shared(dst);
    asm volatile("cp.async.cg.shared.global [%0], [%1], 16;\n" :: "r"(d), "l"(src));
}
#define CP_COMMIT() asm volatile("cp.async.commit_group;\n" ::: "memory")
#define CP_WAIT0()  asm volatile("cp.async.wait_group 0;\n" ::: "memory")
#define CP_WAIT1()  asm volatile("cp.async.wait_group 1;\n" ::: "memory")

#define SCQ (0.125f * 1.44269504f)   // 1/sqrt(dh) * log2(e), folded into Q

// ---------------------------------------------------------------------------
// Mask dtype sniffer + expander (bool may arrive as u8 / i32 / f32)
// ---------------------------------------------------------------------------
__global__ void mask_expand_kernel(const unsigned char* __restrict__ raw) {
    __shared__ int s_not_int, s_not_float;
    if (threadIdx.x == 0) { s_not_int = 0; s_not_float = 0; }
    __syncthreads();
    const unsigned int* w = (const unsigned int*)raw;
    for (int i = threadIdx.x; i < 1024; i += blockDim.x) {
        unsigned int x = w[i];
        if (x != 0u && x != 1u)          atomicOr(&s_not_int, 1);
        if (x != 0u && x != 0x3F800000u) atomicOr(&s_not_float, 1);
    }
    __syncthreads();
    int mode = (!s_not_int) ? 0 : ((!s_not_float) ? 1 : 2);
    if (mode == 2) {
        for (int i = threadIdx.x; i < B_ * N_; i += blockDim.x)
            g_mask[i] = raw[i] ? 1 : 0;
    } else {
        for (int i = threadIdx.x; i < B_ * N_; i += blockDim.x)
            g_mask[i] = w[i] ? 1 : 0;
    }
}

// ---------------------------------------------------------------------------
// TF32 GEMM (R4-proven 2-stage): C = A[.,1024] @ B[1024,1024], 128x128 tile,
// BK=16, cp.async double buffer, 256 thr, __launch_bounds__(256,2).
// Epilogue MODE: 0 = plain fp32, 1 = tf32-rounded bits, 2 = tf32(acc*SCQ).
// ---------------------------------------------------------------------------
#define GA_STR 20
#define GB_STR 136
#define GA_WORDS (128 * GA_STR)
#define GB_WORDS (16 * GB_STR)

__device__ __forceinline__ void gemm_stage_load(
    const float* __restrict__ A, const float* __restrict__ Bm,
    int rowBase, int colBase, int k0, float* As, float* Bs, int tid)
{
#pragma unroll
    for (int i = 0; i < 2; ++i) {
        int f = tid + i * 256;
        int r = f >> 2, c = (f & 3) * 4;
        cpasync16(As + r * GA_STR + c, A + (size_t)(rowBase + r) * D_ + k0 + c);
    }
#pragma unroll
    for (int i = 0; i < 2; ++i) {
        int f = tid + i * 256;
        int r = f >> 5, c = (f & 31) * 4;
        cpasync16(Bs + r * GB_STR + c, Bm + (size_t)(k0 + r) * D_ + colBase + c);
    }
}

template<int MODE>
__device__ __forceinline__ void gemm_body(
    const float* __restrict__ A, const float* __restrict__ Bm, float* __restrict__ C)
{
    __shared__ float As[2][GA_WORDS];
    __shared__ float Bs[2][GB_WORDS];

    const int tid  = threadIdx.x;
    const int warp = tid >> 5, lane = tid & 31;
    const int g = lane >> 2, t = lane & 3;
    const int wm = (warp >> 2) * 64;
    const int wn = (warp & 3) * 32;
    const int rowBase = blockIdx.y * 128;
    const int colBase = blockIdx.x * 128;

    float acc[4][4][4];
#pragma unroll
    for (int i = 0; i < 4; ++i)
#pragma unroll
        for (int j = 0; j < 4; ++j)
#pragma unroll
            for (int k = 0; k < 4; ++k) acc[i][j][k] = 0.f;

    gemm_stage_load(A, Bm, rowBase, colBase, 0, As[0], Bs[0], tid);
    CP_COMMIT();

    const int NIT = D_ / 16;   // 64
    for (int it = 0; it < NIT; ++it) {
        const int cur = it & 1;
        if (it + 1 < NIT) {
            gemm_stage_load(A, Bm, rowBase, colBase, (it + 1) * 16,
                            As[cur ^ 1], Bs[cur ^ 1], tid);
            CP_COMMIT();
            CP_WAIT1();
        } else {
            CP_WAIT0();
        }
        __syncthreads();

        const float* Ac = As[cur];
        const float* Bc = Bs[cur];
#pragma unroll
        for (int kk = 0; kk < 2; ++kk) {
            const int kb = kk * 8;
            unsigned a[4][4], bf[4][2];
#pragma unroll
            for (int mt = 0; mt < 4; ++mt) {
                int mr = wm + mt * 16;
                a[mt][0] = f2tf(Ac[(mr + g) * GA_STR + kb + t]);
                a[mt][1] = f2tf(Ac[(mr + g + 8) * GA_STR + kb + t]);
                a[mt][2] = f2tf(Ac[(mr + g) * GA_STR + kb + t + 4]);
                a[mt][3] = f2tf(Ac[(mr + g + 8) * GA_STR + kb + t + 4]);
            }
#pragma unroll
            for (int nt = 0; nt < 4; ++nt) {
                int nc = wn + nt * 8 + g;
                bf[nt][0] = f2tf(Bc[(kb + t) * GB_STR + nc]);
                bf[nt][1] = f2tf(Bc[(kb + t + 4) * GB_STR + nc]);
            }
#pragma unroll
            for (int mt = 0; mt < 4; ++mt)
#pragma unroll
                for (int nt = 0; nt < 4; ++nt)
                    mma8(acc[mt][nt], a[mt][0], a[mt][1], a[mt][2], a[mt][3],
                         bf[nt][0], bf[nt][1]);
        }
        __syncthreads();
    }

#pragma unroll
    for (int mt = 0; mt < 4; ++mt) {
        int r0 = rowBase + wm + mt * 16 + g;
#pragma unroll
        for (int nt = 0; nt < 4; ++nt) {
            int c0 = colBase + wn + nt * 8 + 2 * t;
            float v0 = acc[mt][nt][0], v1 = acc[mt][nt][1];
            float v2 = acc[mt][nt][2], v3 = acc[mt][nt][3];
            if (MODE == 2) { v0 *= SCQ; v1 *= SCQ; v2 *= SCQ; v3 *= SCQ; }
            if (MODE != 0) {
                v0 = __uint_as_float(f2tf(v0));
                v1 = __uint_as_float(f2tf(v1));
                v2 = __uint_as_float(f2tf(v2));
                v3 = __uint_as_float(f2tf(v3));
            }
            *(float2*)(C + (size_t)r0 * D_ + c0)       = make_float2(v0, v1);
            *(float2*)(C + (size_t)(r0 + 8) * D_ + c0) = make_float2(v2, v3);
        }
    }
}

__global__ __launch_bounds__(256, 2) void gemm_qkv(
    const float* __restrict__ q, const float* __restrict__ kv,
    const float* __restrict__ WQ, const float* __restrict__ WK,
    const float* __restrict__ WV)
{
    if (blockIdx.z == 0)      gemm_body<2>(q,  WQ, g_Q);
    else if (blockIdx.z == 1) gemm_body<1>(kv, WK, g_K);
    else                      gemm_body<1>(kv, WV, g_V);
}

__global__ __launch_bounds__(256, 2) void gemm_single(
    const float* __restrict__ A, const float* __restrict__ Bm, float* __restrict__ C)
{
    gemm_body<0>(A, Bm, C);
}

// ---------------------------------------------------------------------------
// TF32 flash attention, split-K across warp pairs.
// Block = 64 query rows of one (b,h); 8 warps = 4 m-tiles x 2 key-halves.
// Warp (mi, half) processes keys [half*32, half*32+32) of every 64-key tile,
// keeping private online-softmax state; states merged at the end.
// K/V cp.async double-buffered, carrying pre-rounded tf32 bits.
// Grid: (M/64, NH, B), 256 threads.
// ---------------------------------------------------------------------------
#define AQ_STR 68
#define AK_STR 68
#define AV_STR 72
#define AP_STR 68
#define AQ_OFF 0
#define AK_OFF (64 * AQ_STR)
#define AK_STAGE (64 * AK_STR)
#define AV_OFF (AK_OFF + 2 * AK_STAGE)
#define AV_STAGE (64 * AV_STR)
#define AP_OFF (AV_OFF + 2 * AV_STAGE)
#define AMB_OFF (AP_OFF + 64 * AP_STR)
#define AML_OFF (AMB_OFF + 64)
#define ATT_WORDS (AML_OFF + 128)         // 26816 words = 107264 B

#define M_INIT (-1.0e4f)
#define MASK_BIAS (-1.0e9f)

__global__ __launch_bounds__(256, 2) void attn_tc(
    const float* __restrict__ Q, const float* __restrict__ K,
    const float* __restrict__ V, float* __restrict__ Cout)
{
    extern __shared__ unsigned smemu[];
    unsigned* Qs = smemu + AQ_OFF;
    unsigned* Kr = smemu + AK_OFF;
    unsigned* Vr = smemu + AV_OFF;
    unsigned* Ps = smemu + AP_OFF;
    float* mbias = (float*)(smemu + AMB_OFF);
    float* mlbuf = (float*)(smemu + AML_OFF);   // per-row (m,l) of half-1 warps

    const int mtile = blockIdx.x, h = blockIdx.y, b = blockIdx.z;
    const int tid = threadIdx.x;
    const int warp = tid >> 5, lane = tid & 31;
    const int g = lane >> 2, t = lane & 3;
    const int mi = warp & 3, half = warp >> 2;
    const int mb = mi * 16;
    const int kbase = half * 32;
    const int lr = tid >> 2, lch = (tid & 3) * 16;   // loader: 64 rows x 4x16 floats

    const float* Qbase = Q + ((size_t)(b * M_ + mtile * 64)) * D_ + h * DH_;
    const float* Kbase = K + ((size_t)b * N_) * D_ + h * DH_;
    const float* Vbase = V + ((size_t)b * N_) * D_ + h * DH_;

    // Preload group 0: Q tile + K/V tile 0 (pre-rounded tf32 bits)
    {
        const float* qs = Qbase + (size_t)lr * D_ + lch;
        const float* ks = Kbase + (size_t)lr * D_ + lch;
        const float* vs = Vbase + (size_t)lr * D_ + lch;
        unsigned* qd = Qs + lr * AQ_STR + lch;
        unsigned* kd = Kr + lr * AK_STR + lch;
        unsigned* vd = Vr + lr * AV_STR + lch;
#pragma unroll
        for (int i = 0; i < 4; ++i) cpasync16(qd + 4 * i, qs + 4 * i);
#pragma unroll
        for (int i = 0; i < 4; ++i) cpasync16(kd + 4 * i, ks + 4 * i);
#pragma unroll
        for (int i = 0; i < 4; ++i) cpasync16(vd + 4 * i, vs + 4 * i);
    }
    CP_COMMIT();

    float m0 = M_INIT, m1 = M_INIT, l0 = 0.f, l1 = 0.f;
    float o[8][4];
#pragma unroll
    for (int i = 0; i < 8; ++i)
#pragma unroll
        for (int j = 0; j < 4; ++j) o[i][j] = 0.f;

    const int NT = N_ / 64;  // 32
    for (int kt = 0; kt < NT; ++kt) {
        const int cur = kt & 1;
        if (kt + 1 < NT) {
            const int nrow = (kt + 1) * 64 + lr;
            const float* ks = Kbase + (size_t)nrow * D_ + lch;
            const float* vs = Vbase + (size_t)nrow * D_ + lch;
            unsigned* kd = Kr + (cur ^ 1) * AK_STAGE + lr * AK_STR + lch;
            unsigned* vd = Vr + (cur ^ 1) * AV_STAGE + lr * AV_STR + lch;
#pragma unroll
            for (int i = 0; i < 4; ++i) cpasync16(kd + 4 * i, ks + 4 * i);
#pragma unroll
            for (int i = 0; i < 4; ++i) cpasync16(vd + 4 * i, vs + 4 * i);
            CP_COMMIT();
        }
        if (tid < 64)
            mbias[tid] = g_mask[b * N_ + kt * 64 + tid] ? MASK_BIAS : 0.f;
        if (kt + 1 < NT) CP_WAIT1(); else CP_WAIT0();
        __syncthreads();

        const unsigned* Kc = Kr + cur * AK_STAGE;
        const unsigned* Vc = Vr + cur * AV_STAGE;

        // S = Q K^T for this warp's 32-key half (m16 x n32, k=64)
        float s[4][4];
#pragma unroll
        for (int i = 0; i < 4; ++i)
#pragma unroll
            for (int j = 0; j < 4; ++j) s[i][j] = 0.f;

#pragma unroll
        for (int kk = 0; kk < 8; ++kk) {
            const int kb = kk * 8;
            unsigned a0 = Qs[(mb + g) * AQ_STR + kb + t];
            unsigned a1 = Qs[(mb + g + 8) * AQ_STR + kb + t];
            unsigned a2 = Qs[(mb + g) * AQ_STR + kb + t + 4];
            unsigned a3 = Qs[(mb + g + 8) * AQ_STR + kb + t + 4];
#pragma unroll
            for (int nt = 0; nt < 4; ++nt) {
                const int kr = kbase + nt * 8 + g;
                unsigned b0 = Kc[kr * AK_STR + kb + t];
                unsigned b1 = Kc[kr * AK_STR + kb + t + 4];
                mma8(s[nt], a0, a1, a2, a3, b0, b1);
            }
        }

        // online softmax (base-2) over this half
        float mx0 = -3.0e38f, mx1 = -3.0e38f;
#pragma unroll
        for (int nt = 0; nt < 4; ++nt) {
            float b0 = mbias[kbase + nt * 8 + 2 * t];
            float b1 = mbias[kbase + nt * 8 + 2 * t + 1];
            s[nt][0] += b0; s[nt][1] += b1;
            s[nt][2] += b0; s[nt][3] += b1;
            mx0 = fmaxf(mx0, fmaxf(s[nt][0], s[nt][1]));
            mx1 = fmaxf(mx1, fmaxf(s[nt][2], s[nt][3]));
        }
        mx0 = fmaxf(mx0, __shfl_xor_sync(0xFFFFFFFFu, mx0, 1));
        mx0 = fmaxf(mx0, __shfl_xor_sync(0xFFFFFFFFu, mx0, 2));
        mx1 = fmaxf(mx1, __shfl_xor_sync(0xFFFFFFFFu, mx1, 1));
        mx1 = fmaxf(mx1, __shfl_xor_sync(0xFFFFFFFFu, mx1, 2));
        float nm0 = fmaxf(m0, mx0), nm1 = fmaxf(m1, mx1);
        float cr0 = ex2(m0 - nm0), cr1 = ex2(m1 - nm1);
        m0 = nm0; m1 = nm1;

        float rs0 = 0.f, rs1 = 0.f;
#pragma unroll
        for (int nt = 0; nt < 4; ++nt) {
            s[nt][0] = ex2(s[nt][0] - nm0);
            s[nt][1] = ex2(s[nt][1] - nm0);
            s[nt][2] = ex2(s[nt][2] - nm1);
            s[nt][3] = ex2(s[nt][3] - nm1);
            rs0 += s[nt][0] + s[nt][1];
            rs1 += s[nt][2] + s[nt][3];
        }
        l0 = l0 * cr0 + rs0;
        l1 = l1 * cr1 + rs1;

        // rescale O, write P (tf32) into this warp's column range
#pragma unroll
        for (int nt = 0; nt < 8; ++nt) {
            o[nt][0] *= cr0; o[nt][1] *= cr0;
            o[nt][2] *= cr1; o[nt][3] *= cr1;
        }
#pragma unroll
        for (int nt = 0; nt < 4; ++nt) {
            const int pc = kbase + nt * 8 + 2 * t;
            Ps[(mb + g) * AP_STR + pc]         = f2tf(s[nt][0]);
            Ps[(mb + g) * AP_STR + pc + 1]     = f2tf(s[nt][1]);
            Ps[(mb + g + 8) * AP_STR + pc]     = f2tf(s[nt][2]);
            Ps[(mb + g + 8) * AP_STR + pc + 1] = f2tf(s[nt][3]);
        }
        __syncwarp();

        // O += P V over this warp's 32 keys (m16 x n64(dh), k=32)
#pragma unroll
        for (int kk = 0; kk < 4; ++kk) {
            const int kb = kbase + kk * 8;
            unsigned a0 = Ps[(mb + g) * AP_STR + kb + t];
            unsigned a1 = Ps[(mb + g + 8) * AP_STR + kb + t];
            unsigned a2 = Ps[(mb + g) * AP_STR + kb + t + 4];
            unsigned a3 = Ps[(mb + g + 8) * AP_STR + kb + t + 4];
#pragma unroll
            for (int nt = 0; nt < 8; ++nt) {
                unsigned b0 = Vc[(kb + t) * AV_STR + nt * 8 + g];
                unsigned b1 = Vc[(kb + t + 4) * AV_STR + nt * 8 + g];
                mma8(o[nt], a0, a1, a2, a3, b0, b1);
            }
        }
        __syncthreads();   // stage + Ps fully consumed before reuse
    }

    // reduce l across the quad (t lanes)
    l0 += __shfl_xor_sync(0xFFFFFFFFu, l0, 1);
    l0 += __shfl_xor_sync(0xFFFFFFFFu, l0, 2);
    l1 += __shfl_xor_sync(0xFFFFFFFFu, l1, 1);
    l1 += __shfl_xor_sync(0xFFFFFFFFu, l1, 2);

    // merge the two key-halves of each m-tile
    float* Obuf = (float*)Ps;     // reuse P buffer (64 x AP_STR floats)
    if (half == 1) {
#pragma unroll
        for (int nt = 0; nt < 8; ++nt) {
            const int c = nt * 8 + 2 * t;
            Obuf[(mb + g) * AP_STR + c]         = o[nt][0];
            Obuf[(mb + g) * AP_STR + c + 1]     = o[nt][1];
            Obuf[(mb + g + 8) * AP_STR + c]     = o[nt][2];
            Obuf[(mb + g + 8) * AP_STR + c + 1] = o[nt][3];
        }
        if (t == 0) {
            mlbuf[(mb + g) * 2]     = m0;
            mlbuf[(mb + g) * 2 + 1] = l0;
            mlbuf[(mb + g + 8) * 2]     = m1;
            mlbuf[(mb + g + 8) * 2 + 1] = l1;
        }
    }
    __syncthreads();
    if (half == 0) {
        float mp0 = mlbuf[(mb + g) * 2],     lp0 = mlbuf[(mb + g) * 2 + 1];
        float mp1 = mlbuf[(mb + g + 8) * 2], lp1 = mlbuf[(mb + g + 8) * 2 + 1];
        float ms0 = fmaxf(m0, mp0), ms1 = fmaxf(m1, mp1);
        float ca0 = ex2(m0 - ms0), cb0 = ex2(mp0 - ms0);
        float ca1 = ex2(m1 - ms1), cb1 = ex2(mp1 - ms1);
        float inv0 = 1.f / (l0 * ca0 + lp0 * cb0);
        float inv1 = 1.f / (l1 * ca1 + lp1 * cb1);

        const int gr0 = mtile * 64 + mb + g;
        const int gr1 = gr0 + 8;
#pragma unroll
        for (int nt = 0; nt < 8; ++nt) {
            const int c = nt * 8 + 2 * t;
            float p00 = Obuf[(mb + g) * AP_STR + c];
            float p01 = Obuf[(mb + g) * AP_STR + c + 1];
            float p10 = Obuf[(mb + g + 8) * AP_STR + c];
            float p11 = Obuf[(mb + g + 8) * AP_STR + c + 1];
            int col = h * DH_ + c;
            *(float2*)(Cout + ((size_t)(b * M_ + gr0)) * D_ + col) =
                make_float2((o[nt][0] * ca0 + p00 * cb0) * inv0,
                            (o[nt][1] * ca0 + p01 * cb0) * inv0);
            *(float2*)(Cout + ((size_t)(b * M_ + gr1)) * D_ + col) =
                make_float2((o[nt][2] * ca1 + p10 * cb1) * inv1,
                            (o[nt][3] * ca1 + p11 * cb1) * inv1);
        }
    }
}

// ---------------------------------------------------------------------------
// Launch. Inputs: query, key_value, key_padding_mask, W_Q, W_K, W_V, W_O
// ---------------------------------------------------------------------------
extern "C" void kernel_launch(void* const* d_in, const int* in_sizes, int n_in,
                              void* d_out, int out_size)
{
    const float* query = (const float*)d_in[0];
    const float* keyv  = (const float*)d_in[1];
    const unsigned char* mask_raw = (const unsigned char*)d_in[2];
    const float* W_Q = (const float*)d_in[3];
    const float* W_K = (const float*)d_in[4];
    const float* W_V = (const float*)d_in[5];
    const float* W_O = (const float*)d_in[6];
    float* out = (float*)d_out;

    float *gQ, *gK, *gV, *gC;
    cudaGetSymbolAddress((void**)&gQ, g_Q);
    cudaGetSymbolAddress((void**)&gK, g_K);
    cudaGetSymbolAddress((void**)&gV, g_V);
    cudaGetSymbolAddress((void**)&gC, g_C);

    cudaFuncSetAttribute(attn_tc, cudaFuncAttributeMaxDynamicSharedMemorySize,
                         ATT_WORDS * 4);

    mask_expand_kernel<<<1, 1024>>>(mask_raw);

    dim3 gqkv(D_ / 128, (B_ * M_) / 128, 3);
    gemm_qkv<<<gqkv, 256>>>(query, keyv, W_Q, W_K, W_V);

    dim3 gattn(M_ / 64, NH_, B_);
    attn_tc<<<gattn, 256, ATT_WORDS * 4>>>(gQ, gK, gV, gC);

    dim3 gout(D_ / 128, (B_ * M_) / 128);
    gemm_single<<<gout, 256>>>(gC, W_O, out);
}

// round 8
// speedup vs baseline: 1.3914x; 1.3914x over previous
#include <cuda_runtime.h>
#include <stdint.h>

#define B_  2
#define M_  2048
#define N_  2048
#define D_  1024
#define NH_ 16
#define DH_ 64

// Scratch (device globals: no allocation allowed)
// g_Q holds tf32-rounded (Q*scale*log2e) bits; g_K/g_V hold tf32-rounded bits.
__device__ float g_Q[(size_t)B_ * M_ * D_];
__device__ float g_K[(size_t)B_ * N_ * D_];
__device__ float g_V[(size_t)B_ * N_ * D_];
__device__ float g_C[(size_t)B_ * M_ * D_];
__device__ unsigned char g_mask[B_ * N_];

// ---------------------------------------------------------------------------
// helpers
// ---------------------------------------------------------------------------
__device__ __forceinline__ unsigned f2tf(float x) {
    unsigned u; asm("cvt.rna.tf32.f32 %0, %1;" : "=r"(u) : "f"(x)); return u;
}
__device__ __forceinline__ float ex2(float x) {
    float y; asm("ex2.approx.f32 %0, %1;" : "=f"(y) : "f"(x)); return y;
}
__device__ __forceinline__ void mma8(float* c, unsigned a0, unsigned a1, unsigned a2, unsigned a3,
                                     unsigned b0, unsigned b1) {
    asm volatile(
        "mma.sync.aligned.m16n8k8.row.col.f32.tf32.tf32.f32 "
        "{%0,%1,%2,%3},{%4,%5,%6,%7},{%8,%9},{%0,%1,%2,%3};\n"
        : "+f"(c[0]), "+f"(c[1]), "+f"(c[2]), "+f"(c[3])
        : "r"(a0), "r"(a1), "r"(a2), "r"(a3), "r"(b0), "r"(b1));
}
__device__ __forceinline__ void cpasync16(void* dst, const void* src) {
    unsigned d = (unsigned)__cvta_generic_to_shared(dst);
    asm volatile("cp.async.cg.shared.global [%0], [%1], 16;\n" :: "r"(d), "l"(src));
}
#define CP_COMMIT() asm volatile("cp.async.commit_group;\n" ::: "memory")
#define CP_WAIT0()  asm volatile("cp.async.wait_group 0;\n" ::: "memory")
#define CP_WAIT1()  asm volatile("cp.async.wait_group 1;\n" ::: "memory")

#define SCQ (0.125f * 1.44269504f)   // 1/sqrt(dh) * log2(e), folded into Q

// ---------------------------------------------------------------------------
// Mask dtype sniffer + expander (bool may arrive as u8 / i32 / f32)
// ---------------------------------------------------------------------------
__global__ void mask_expand_kernel(const unsigned char* __restrict__ raw) {
    __shared__ int s_not_int, s_not_float;
    if (threadIdx.x == 0) { s_not_int = 0; s_not_float = 0; }
    __syncthreads();
    const unsigned int* w = (const unsigned int*)raw;
    for (int i = threadIdx.x; i < 1024; i += blockDim.x) {
        unsigned int x = w[i];
        if (x != 0u && x != 1u)          atomicOr(&s_not_int, 1);
        if (x != 0u && x != 0x3F800000u) atomicOr(&s_not_float, 1);
    }
    __syncthreads();
    int mode = (!s_not_int) ? 0 : ((!s_not_float) ? 1 : 2);
    if (mode == 2) {
        for (int i = threadIdx.x; i < B_ * N_; i += blockDim.x)
            g_mask[i] = raw[i] ? 1 : 0;
    } else {
        for (int i = threadIdx.x; i < B_ * N_; i += blockDim.x)
            g_mask[i] = w[i] ? 1 : 0;
    }
}

// ---------------------------------------------------------------------------
// TF32 GEMM (R4/R6-proven 2-stage): C = A[.,1024] @ B[1024,1024], 128x128
// tile, BK=16, cp.async double buffer, 256 thr, __launch_bounds__(256,2).
// Epilogue MODE: 0 = plain fp32, 1 = tf32-rounded bits, 2 = tf32(acc*SCQ).
// ---------------------------------------------------------------------------
#define GA_STR 20
#define GB_STR 136
#define GA_WORDS (128 * GA_STR)
#define GB_WORDS (16 * GB_STR)

__device__ __forceinline__ void gemm_stage_load(
    const float* __restrict__ A, const float* __restrict__ Bm,
    int rowBase, int colBase, int k0, float* As, float* Bs, int tid)
{
#pragma unroll
    for (int i = 0; i < 2; ++i) {
        int f = tid + i * 256;
        int r = f >> 2, c = (f & 3) * 4;
        cpasync16(As + r * GA_STR + c, A + (size_t)(rowBase + r) * D_ + k0 + c);
    }
#pragma unroll
    for (int i = 0; i < 2; ++i) {
        int f = tid + i * 256;
        int r = f >> 5, c = (f & 31) * 4;
        cpasync16(Bs + r * GB_STR + c, Bm + (size_t)(k0 + r) * D_ + colBase + c);
    }
}

template<int MODE>
__device__ __forceinline__ void gemm_body(
    const float* __restrict__ A, const float* __restrict__ Bm, float* __restrict__ C)
{
    __shared__ float As[2][GA_WORDS];
    __shared__ float Bs[2][GB_WORDS];

    const int tid  = threadIdx.x;
    const int warp = tid >> 5, lane = tid & 31;
    const int g = lane >> 2, t = lane & 3;
    const int wm = (warp >> 2) * 64;
    const int wn = (warp & 3) * 32;
    const int rowBase = blockIdx.y * 128;
    const int colBase = blockIdx.x * 128;

    float acc[4][4][4];
#pragma unroll
    for (int i = 0; i < 4; ++i)
#pragma unroll
        for (int j = 0; j < 4; ++j)
#pragma unroll
            for (int k = 0; k < 4; ++k) acc[i][j][k] = 0.f;

    gemm_stage_load(A, Bm, rowBase, colBase, 0, As[0], Bs[0], tid);
    CP_COMMIT();

    const int NIT = D_ / 16;   // 64
    for (int it = 0; it < NIT; ++it) {
        const int cur = it & 1;
        if (it + 1 < NIT) {
            gemm_stage_load(A, Bm, rowBase, colBase, (it + 1) * 16,
                            As[cur ^ 1], Bs[cur ^ 1], tid);
            CP_COMMIT();
            CP_WAIT1();
        } else {
            CP_WAIT0();
        }
        __syncthreads();

        const float* Ac = As[cur];
        const float* Bc = Bs[cur];
#pragma unroll
        for (int kk = 0; kk < 2; ++kk) {
            const int kb = kk * 8;
            unsigned a[4][4], bf[4][2];
#pragma unroll
            for (int mt = 0; mt < 4; ++mt) {
                int mr = wm + mt * 16;
                a[mt][0] = f2tf(Ac[(mr + g) * GA_STR + kb + t]);
                a[mt][1] = f2tf(Ac[(mr + g + 8) * GA_STR + kb + t]);
                a[mt][2] = f2tf(Ac[(mr + g) * GA_STR + kb + t + 4]);
                a[mt][3] = f2tf(Ac[(mr + g + 8) * GA_STR + kb + t + 4]);
            }
#pragma unroll
            for (int nt = 0; nt < 4; ++nt) {
                int nc = wn + nt * 8 + g;
                bf[nt][0] = f2tf(Bc[(kb + t) * GB_STR + nc]);
                bf[nt][1] = f2tf(Bc[(kb + t + 4) * GB_STR + nc]);
            }
#pragma unroll
            for (int mt = 0; mt < 4; ++mt)
#pragma unroll
                for (int nt = 0; nt < 4; ++nt)
                    mma8(acc[mt][nt], a[mt][0], a[mt][1], a[mt][2], a[mt][3],
                         bf[nt][0], bf[nt][1]);
        }
        __syncthreads();
    }

#pragma unroll
    for (int mt = 0; mt < 4; ++mt) {
        int r0 = rowBase + wm + mt * 16 + g;
#pragma unroll
        for (int nt = 0; nt < 4; ++nt) {
            int c0 = colBase + wn + nt * 8 + 2 * t;
            float v0 = acc[mt][nt][0], v1 = acc[mt][nt][1];
            float v2 = acc[mt][nt][2], v3 = acc[mt][nt][3];
            if (MODE == 2) { v0 *= SCQ; v1 *= SCQ; v2 *= SCQ; v3 *= SCQ; }
            if (MODE != 0) {
                v0 = __uint_as_float(f2tf(v0));
                v1 = __uint_as_float(f2tf(v1));
                v2 = __uint_as_float(f2tf(v2));
                v3 = __uint_as_float(f2tf(v3));
            }
            *(float2*)(C + (size_t)r0 * D_ + c0)       = make_float2(v0, v1);
            *(float2*)(C + (size_t)(r0 + 8) * D_ + c0) = make_float2(v2, v3);
        }
    }
}

__global__ __launch_bounds__(256, 2) void gemm_qkv(
    const float* __restrict__ q, const float* __restrict__ kv,
    const float* __restrict__ WQ, const float* __restrict__ WK,
    const float* __restrict__ WV)
{
    if (blockIdx.z == 0)      gemm_body<2>(q,  WQ, g_Q);
    else if (blockIdx.z == 1) gemm_body<1>(kv, WK, g_K);
    else                      gemm_body<1>(kv, WV, g_V);
}

__global__ __launch_bounds__(256, 2) void gemm_single(
    const float* __restrict__ A, const float* __restrict__ Bm, float* __restrict__ C)
{
    gemm_body<0>(A, Bm, C);
}

// ---------------------------------------------------------------------------
// TF32 flash attention (R6 structure) with Q a-fragments register-resident.
// Block = 64 query rows of one (b,h), 4 warps x 16 rows. K/V cp.async
// double-buffered carrying pre-rounded tf32 bits. Grid: (M/64, NH, B).
// Smem ~89KB -> 2 blocks/SM; 128-thread blocks leave full 255-reg headroom.
// ---------------------------------------------------------------------------
#define AK_STR 68
#define AV_STR 72
#define AP_STR 68
#define AK_OFF 0
#define AK_STAGE (64 * AK_STR)                  // 4352
#define AV_OFF (2 * AK_STAGE)                   // 8704
#define AV_STAGE (64 * AV_STR)                  // 4608
#define AP_OFF (AV_OFF + 2 * AV_STAGE)          // 17920
#define AMB_OFF (AP_OFF + 64 * AP_STR)          // 22272
#define ATT_WORDS (AMB_OFF + 64)                // 22336 words = 89344 B

#define M_INIT (-1.0e4f)
#define MASK_BIAS (-1.0e9f)

__global__ __launch_bounds__(128) void attn_tc(
    const float* __restrict__ Q, const float* __restrict__ K,
    const float* __restrict__ V, float* __restrict__ Cout)
{
    extern __shared__ unsigned smemu[];
    unsigned* Kr = smemu + AK_OFF;        // tf32 bits, 2 stages
    unsigned* Vr = smemu + AV_OFF;        // tf32 bits, 2 stages
    unsigned* Ps = smemu + AP_OFF;        // tf32 bits
    float* mbias = (float*)(smemu + AMB_OFF);

    const int mtile = blockIdx.x, h = blockIdx.y, b = blockIdx.z;
    const int tid = threadIdx.x;
    const int warp = tid >> 5, lane = tid & 31;
    const int g = lane >> 2, t = lane & 3;
    const int mb = warp * 16;
    const int lr = tid >> 1, lch = (tid & 1) * 32;

    const float* Kbase = K + ((size_t)b * N_) * D_ + h * DH_;
    const float* Vbase = V + ((size_t)b * N_) * D_ + h * DH_;

    // Async preload of K/V tile 0 first — overlaps the Q register loads below.
    {
        const float* ks = Kbase + (size_t)lr * D_ + lch;
        const float* vs = Vbase + (size_t)lr * D_ + lch;
        unsigned* kd = Kr + lr * AK_STR + lch;
        unsigned* vd = Vr + lr * AV_STR + lch;
#pragma unroll
        for (int i = 0; i < 8; ++i) cpasync16(kd + 4 * i, ks + 4 * i);
#pragma unroll
        for (int i = 0; i < 8; ++i) cpasync16(vd + 4 * i, vs + 4 * i);
    }
    CP_COMMIT();

    // Q a-fragments: one-time global load of pre-rounded (scaled) tf32 bits.
    // qa[kk] = {Q[r0, kb+t], Q[r1, kb+t], Q[r0, kb+t+4], Q[r1, kb+t+4]}
    unsigned qa[8][4];
    {
        const unsigned* q0 = (const unsigned*)(Q + ((size_t)(b * M_ + mtile * 64 + mb + g)) * D_ + h * DH_);
        const unsigned* q1 = (const unsigned*)(Q + ((size_t)(b * M_ + mtile * 64 + mb + g + 8)) * D_ + h * DH_);
#pragma unroll
        for (int kk = 0; kk < 8; ++kk) {
            const int kb = kk * 8;
            qa[kk][0] = q0[kb + t];
            qa[kk][1] = q1[kb + t];
            qa[kk][2] = q0[kb + t + 4];
            qa[kk][3] = q1[kb + t + 4];
        }
    }

    float m0 = M_INIT, m1 = M_INIT, l0 = 0.f, l1 = 0.f;
    float o[8][4];
#pragma unroll
    for (int i = 0; i < 8; ++i)
#pragma unroll
        for (int j = 0; j < 4; ++j) o[i][j] = 0.f;

    const int NT = N_ / 64;  // 32
    for (int kt = 0; kt < NT; ++kt) {
        const int cur = kt & 1;
        if (kt + 1 < NT) {
            const int nrow = (kt + 1) * 64 + lr;
            const float* ks = Kbase + (size_t)nrow * D_ + lch;
            const float* vs = Vbase + (size_t)nrow * D_ + lch;
            unsigned* kd = Kr + (cur ^ 1) * AK_STAGE + lr * AK_STR + lch;
            unsigned* vd = Vr + (cur ^ 1) * AV_STAGE + lr * AV_STR + lch;
#pragma unroll
            for (int i = 0; i < 8; ++i) cpasync16(kd + 4 * i, ks + 4 * i);
#pragma unroll
            for (int i = 0; i < 8; ++i) cpasync16(vd + 4 * i, vs + 4 * i);
            CP_COMMIT();
        }
        if (tid < 64)
            mbias[tid] = g_mask[b * N_ + kt * 64 + tid] ? MASK_BIAS : 0.f;
        if (kt + 1 < NT) CP_WAIT1(); else CP_WAIT0();
        __syncthreads();

        const unsigned* Kc = Kr + cur * AK_STAGE;
        const unsigned* Vc = Vr + cur * AV_STAGE;

        // S = Q K^T  (A operands already in registers)
        float s[8][4];
#pragma unroll
        for (int i = 0; i < 8; ++i)
#pragma unroll
            for (int j = 0; j < 4; ++j) s[i][j] = 0.f;

#pragma unroll
        for (int kk = 0; kk < 8; ++kk) {
            const int kb = kk * 8;
#pragma unroll
            for (int nt = 0; nt < 8; ++nt) {
                unsigned b0 = Kc[(nt * 8 + g) * AK_STR + kb + t];
                unsigned b1 = Kc[(nt * 8 + g) * AK_STR + kb + t + 4];
                mma8(s[nt], qa[kk][0], qa[kk][1], qa[kk][2], qa[kk][3], b0, b1);
            }
        }

        // online softmax (base-2)
        float mx0 = -3.0e38f, mx1 = -3.0e38f;
#pragma unroll
        for (int nt = 0; nt < 8; ++nt) {
            float b0 = mbias[nt * 8 + 2 * t];
            float b1 = mbias[nt * 8 + 2 * t + 1];
            s[nt][0] += b0; s[nt][1] += b1;
            s[nt][2] += b0; s[nt][3] += b1;
            mx0 = fmaxf(mx0, fmaxf(s[nt][0], s[nt][1]));
            mx1 = fmaxf(mx1, fmaxf(s[nt][2], s[nt][3]));
        }
        mx0 = fmaxf(mx0, __shfl_xor_sync(0xFFFFFFFFu, mx0, 1));
        mx0 = fmaxf(mx0, __shfl_xor_sync(0xFFFFFFFFu, mx0, 2));
        mx1 = fmaxf(mx1, __shfl_xor_sync(0xFFFFFFFFu, mx1, 1));
        mx1 = fmaxf(mx1, __shfl_xor_sync(0xFFFFFFFFu, mx1, 2));
        float nm0 = fmaxf(m0, mx0), nm1 = fmaxf(m1, mx1);
        float cr0 = ex2(m0 - nm0), cr1 = ex2(m1 - nm1);
        m0 = nm0; m1 = nm1;

        float rs0 = 0.f, rs1 = 0.f;
#pragma unroll
        for (int nt = 0; nt < 8; ++nt) {
            s[nt][0] = ex2(s[nt][0] - nm0);
            s[nt][1] = ex2(s[nt][1] - nm0);
            s[nt][2] = ex2(s[nt][2] - nm1);
            s[nt][3] = ex2(s[nt][3] - nm1);
            rs0 += s[nt][0] + s[nt][1];
            rs1 += s[nt][2] + s[nt][3];
        }
        l0 = l0 * cr0 + rs0;
        l1 = l1 * cr1 + rs1;

#pragma unroll
        for (int nt = 0; nt < 8; ++nt) {
            o[nt][0] *= cr0; o[nt][1] *= cr0;
            o[nt][2] *= cr1; o[nt][3] *= cr1;
            Ps[(mb + g) * AP_STR + nt * 8 + 2 * t]         = f2tf(s[nt][0]);
            Ps[(mb + g) * AP_STR + nt * 8 + 2 * t + 1]     = f2tf(s[nt][1]);
            Ps[(mb + g + 8) * AP_STR + nt * 8 + 2 * t]     = f2tf(s[nt][2]);
            Ps[(mb + g + 8) * AP_STR + nt * 8 + 2 * t + 1] = f2tf(s[nt][3]);
        }
        __syncwarp();

        // O += P V
#pragma unroll
        for (int kk = 0; kk < 8; ++kk) {
            const int kb = kk * 8;
            unsigned a0 = Ps[(mb + g) * AP_STR + kb + t];
            unsigned a1 = Ps[(mb + g + 8) * AP_STR + kb + t];
            unsigned a2 = Ps[(mb + g) * AP_STR + kb + t + 4];
            unsigned a3 = Ps[(mb + g + 8) * AP_STR + kb + t + 4];
#pragma unroll
            for (int nt = 0; nt < 8; ++nt) {
                unsigned b0 = Vc[(kb + t) * AV_STR + nt * 8 + g];
                unsigned b1 = Vc[(kb + t + 4) * AV_STR + nt * 8 + g];
                mma8(o[nt], a0, a1, a2, a3, b0, b1);
            }
        }
        __syncthreads();   // stage fully consumed before reuse
    }

    l0 += __shfl_xor_sync(0xFFFFFFFFu, l0, 1);
    l0 += __shfl_xor_sync(0xFFFFFFFFu, l0, 2);
    l1 += __shfl_xor_sync(0xFFFFFFFFu, l1, 1);
    l1 += __shfl_xor_sync(0xFFFFFFFFu, l1, 2);
    float inv0 = 1.f / l0, inv1 = 1.f / l1;

    const int gr0 = mtile * 64 + mb + g;
    const int gr1 = gr0 + 8;
#pragma unroll
    for (int nt = 0; nt < 8; ++nt) {
        int col = h * DH_ + nt * 8 + 2 * t;
        *(float2*)(Cout + ((size_t)(b * M_ + gr0)) * D_ + col) =
            make_float2(o[nt][0] * inv0, o[nt][1] * inv0);
        *(float2*)(Cout + ((size_t)(b * M_ + gr1)) * D_ + col) =
            make_float2(o[nt][2] * inv1, o[nt][3] * inv1);
    }
}

// ---------------------------------------------------------------------------
// Launch. Inputs: query, key_value, key_padding_mask, W_Q, W_K, W_V, W_O
// ---------------------------------------------------------------------------
extern "C" void kernel_launch(void* const* d_in, const int* in_sizes, int n_in,
                              void* d_out, int out_size)
{
    const float* query = (const float*)d_in[0];
    const float* keyv  = (const float*)d_in[1];
    const unsigned char* mask_raw = (const unsigned char*)d_in[2];
    const float* W_Q = (const float*)d_in[3];
    const float* W_K = (const float*)d_in[4];
    const float* W_V = (const float*)d_in[5];
    const float* W_O = (const float*)d_in[6];
    float* out = (float*)d_out;

    float *gQ, *gK, *gV, *gC;
    cudaGetSymbolAddress((void**)&gQ, g_Q);
    cudaGetSymbolAddress((void**)&gK, g_K);
    cudaGetSymbolAddress((void**)&gV, g_V);
    cudaGetSymbolAddress((void**)&gC, g_C);

    cudaFuncSetAttribute(attn_tc, cudaFuncAttributeMaxDynamicSharedMemorySize,
                         ATT_WORDS * 4);

    mask_expand_kernel<<<1, 1024>>>(mask_raw);

    dim3 gqkv(D_ / 128, (B_ * M_) / 128, 3);
    gemm_qkv<<<gqkv, 256>>>(query, keyv, W_Q, W_K, W_V);

    dim3 gattn(M_ / 64, NH_, B_);
    attn_tc<<<gattn, 128, ATT_WORDS * 4>>>(gQ, gK, gV, gC);

    dim3 gout(D_ / 128, (B_ * M_) / 128);
    gemm_single<<<gout, 256>>>(gC, W_O, out);
}

// round 9
// speedup vs baseline: 1.5223x; 1.0941x over previous
#include <cuda_runtime.h>
#include <stdint.h>

#define B_  2
#define M_  2048
#define N_  2048
#define D_  1024
#define NH_ 16
#define DH_ 64

#define NIN ((size_t)B_ * M_ * D_)   // 4M elems
#define NW  ((size_t)D_ * D_)        // 1M elems

// Scratch (device globals: no allocation allowed).
// All "float" buffers below carry tf32-rounded bit patterns unless noted.
__device__ float g_Q[NIN];           // tf32(Q*scale*log2e) bits
__device__ float g_K[NIN];           // tf32 bits
__device__ float g_V[NIN];           // tf32 bits
__device__ float g_C[NIN];           // tf32 bits (attention output)
__device__ float g_Xq[NIN];          // tf32(query) bits
__device__ float g_Xkv[NIN];         // tf32(key_value) bits
__device__ float g_Wq[NW], g_Wk[NW], g_Wv[NW], g_Wo[NW];   // tf32(weight) bits
__device__ unsigned char g_mask[B_ * N_];

// ---------------------------------------------------------------------------
// helpers
// ---------------------------------------------------------------------------
__device__ __forceinline__ unsigned f2tf(float x) {
    unsigned u; asm("cvt.rna.tf32.f32 %0, %1;" : "=r"(u) : "f"(x)); return u;
}
__device__ __forceinline__ float ex2(float x) {
    float y; asm("ex2.approx.f32 %0, %1;" : "=f"(y) : "f"(x)); return y;
}
__device__ __forceinline__ void mma8(float* c, unsigned a0, unsigned a1, unsigned a2, unsigned a3,
                                     unsigned b0, unsigned b1) {
    asm volatile(
        "mma.sync.aligned.m16n8k8.row.col.f32.tf32.tf32.f32 "
        "{%0,%1,%2,%3},{%4,%5,%6,%7},{%8,%9},{%0,%1,%2,%3};\n"
        : "+f"(c[0]), "+f"(c[1]), "+f"(c[2]), "+f"(c[3])
        : "r"(a0), "r"(a1), "r"(a2), "r"(a3), "r"(b0), "r"(b1));
}
__device__ __forceinline__ void cpasync16(void* dst, const void* src) {
    unsigned d = (unsigned)__cvta_generic_to_shared(dst);
    asm volatile("cp.async.cg.shared.global [%0], [%1], 16;\n" :: "r"(d), "l"(src));
}
#define CP_COMMIT() asm volatile("cp.async.commit_group;\n" ::: "memory")
#define CP_WAIT0()  asm volatile("cp.async.wait_group 0;\n" ::: "memory")
#define CP_WAIT1()  asm volatile("cp.async.wait_group 1;\n" ::: "memory")

#define SCQ (0.125f * 1.44269504f)   // 1/sqrt(dh) * log2(e), folded into Q

// ---------------------------------------------------------------------------
// Mask dtype sniffer + expander (bool may arrive as u8 / i32 / f32)
// ---------------------------------------------------------------------------
__global__ void mask_expand_kernel(const unsigned char* __restrict__ raw) {
    __shared__ int s_not_int, s_not_float;
    if (threadIdx.x == 0) { s_not_int = 0; s_not_float = 0; }
    __syncthreads();
    const unsigned int* w = (const unsigned int*)raw;
    for (int i = threadIdx.x; i < 1024; i += blockDim.x) {
        unsigned int x = w[i];
        if (x != 0u && x != 1u)          atomicOr(&s_not_int, 1);
        if (x != 0u && x != 0x3F800000u) atomicOr(&s_not_float, 1);
    }
    __syncthreads();
    int mode = (!s_not_int) ? 0 : ((!s_not_float) ? 1 : 2);
    if (mode == 2) {
        for (int i = threadIdx.x; i < B_ * N_; i += blockDim.x)
            g_mask[i] = raw[i] ? 1 : 0;
    } else {
        for (int i = threadIdx.x; i < B_ * N_; i += blockDim.x)
            g_mask[i] = w[i] ? 1 : 0;
    }
}

// ---------------------------------------------------------------------------
// One-time tf32 pre-rounding of all GEMM operands (inputs + weights).
// 12M elems as float4; grid covers exactly, guarded anyway.
// ---------------------------------------------------------------------------
__global__ __launch_bounds__(256) void preround_kernel(
    const float* __restrict__ q, const float* __restrict__ kv,
    const float* __restrict__ wq, const float* __restrict__ wk,
    const float* __restrict__ wv, const float* __restrict__ wo)
{
    size_t i4 = (size_t)blockIdx.x * blockDim.x + threadIdx.x;
    const size_t total4 = (2 * NIN + 4 * NW) / 4;   // 3,145,728
    if (i4 >= total4) return;
    size_t off = i4 * 4;
    const float* src; float* dst;
    if (off < NIN)                       { src = q;  dst = g_Xq;  }
    else if ((off -= NIN) < NIN)         { src = kv; dst = g_Xkv; }
    else if ((off -= NIN) < NW)          { src = wq; dst = g_Wq;  }
    else if ((off -= NW) < NW)           { src = wk; dst = g_Wk;  }
    else if ((off -= NW) < NW)           { src = wv; dst = g_Wv;  }
    else         { off -= NW;              src = wo; dst = g_Wo;  }
    float4 v = *(const float4*)(src + off);
    float4 r;
    r.x = __uint_as_float(f2tf(v.x));
    r.y = __uint_as_float(f2tf(v.y));
    r.z = __uint_as_float(f2tf(v.z));
    r.w = __uint_as_float(f2tf(v.w));
    *(float4*)(dst + off) = r;
}

// ---------------------------------------------------------------------------
// TF32 GEMM (R4/R6-proven 2-stage), operands are PRE-ROUNDED tf32 bits:
// zero conversions in the main loop. 128x128 tile, BK=16, cp.async double
// buffer, 256 thr, __launch_bounds__(256,2).
// Epilogue MODE: 0 = plain fp32, 1 = tf32-rounded bits, 2 = tf32(acc*SCQ).
// ---------------------------------------------------------------------------
#define GA_STR 20
#define GB_STR 136
#define GA_WORDS (128 * GA_STR)
#define GB_WORDS (16 * GB_STR)

__device__ __forceinline__ void gemm_stage_load(
    const float* __restrict__ A, const float* __restrict__ Bm,
    int rowBase, int colBase, int k0, float* As, float* Bs, int tid)
{
#pragma unroll
    for (int i = 0; i < 2; ++i) {
        int f = tid + i * 256;
        int r = f >> 2, c = (f & 3) * 4;
        cpasync16(As + r * GA_STR + c, A + (size_t)(rowBase + r) * D_ + k0 + c);
    }
#pragma unroll
    for (int i = 0; i < 2; ++i) {
        int f = tid + i * 256;
        int r = f >> 5, c = (f & 31) * 4;
        cpasync16(Bs + r * GB_STR + c, Bm + (size_t)(k0 + r) * D_ + colBase + c);
    }
}

template<int MODE>
__device__ __forceinline__ void gemm_body(
    const float* __restrict__ A, const float* __restrict__ Bm, float* __restrict__ C)
{
    __shared__ float As[2][GA_WORDS];
    __shared__ float Bs[2][GB_WORDS];

    const int tid  = threadIdx.x;
    const int warp = tid >> 5, lane = tid & 31;
    const int g = lane >> 2, t = lane & 3;
    const int wm = (warp >> 2) * 64;
    const int wn = (warp & 3) * 32;
    const int rowBase = blockIdx.y * 128;
    const int colBase = blockIdx.x * 128;

    float acc[4][4][4];
#pragma unroll
    for (int i = 0; i < 4; ++i)
#pragma unroll
        for (int j = 0; j < 4; ++j)
#pragma unroll
            for (int k = 0; k < 4; ++k) acc[i][j][k] = 0.f;

    gemm_stage_load(A, Bm, rowBase, colBase, 0, As[0], Bs[0], tid);
    CP_COMMIT();

    const int NIT = D_ / 16;   // 64
    for (int it = 0; it < NIT; ++it) {
        const int cur = it & 1;
        if (it + 1 < NIT) {
            gemm_stage_load(A, Bm, rowBase, colBase, (it + 1) * 16,
                            As[cur ^ 1], Bs[cur ^ 1], tid);
            CP_COMMIT();
            CP_WAIT1();
        } else {
            CP_WAIT0();
        }
        __syncthreads();

        const unsigned* Ac = (const unsigned*)As[cur];
        const unsigned* Bc = (const unsigned*)Bs[cur];
#pragma unroll
        for (int kk = 0; kk < 2; ++kk) {
            const int kb = kk * 8;
            unsigned a[4][4], bf[4][2];
#pragma unroll
            for (int mt = 0; mt < 4; ++mt) {
                int mr = wm + mt * 16;
                a[mt][0] = Ac[(mr + g) * GA_STR + kb + t];
                a[mt][1] = Ac[(mr + g + 8) * GA_STR + kb + t];
                a[mt][2] = Ac[(mr + g) * GA_STR + kb + t + 4];
                a[mt][3] = Ac[(mr + g + 8) * GA_STR + kb + t + 4];
            }
#pragma unroll
            for (int nt = 0; nt < 4; ++nt) {
                int nc = wn + nt * 8 + g;
                bf[nt][0] = Bc[(kb + t) * GB_STR + nc];
                bf[nt][1] = Bc[(kb + t + 4) * GB_STR + nc];
            }
#pragma unroll
            for (int mt = 0; mt < 4; ++mt)
#pragma unroll
                for (int nt = 0; nt < 4; ++nt)
                    mma8(acc[mt][nt], a[mt][0], a[mt][1], a[mt][2], a[mt][3],
                         bf[nt][0], bf[nt][1]);
        }
        __syncthreads();
    }

#pragma unroll
    for (int mt = 0; mt < 4; ++mt) {
        int r0 = rowBase + wm + mt * 16 + g;
#pragma unroll
        for (int nt = 0; nt < 4; ++nt) {
            int c0 = colBase + wn + nt * 8 + 2 * t;
            float v0 = acc[mt][nt][0], v1 = acc[mt][nt][1];
            float v2 = acc[mt][nt][2], v3 = acc[mt][nt][3];
            if (MODE == 2) { v0 *= SCQ; v1 *= SCQ; v2 *= SCQ; v3 *= SCQ; }
            if (MODE != 0) {
                v0 = __uint_as_float(f2tf(v0));
                v1 = __uint_as_float(f2tf(v1));
                v2 = __uint_as_float(f2tf(v2));
                v3 = __uint_as_float(f2tf(v3));
            }
            *(float2*)(C + (size_t)r0 * D_ + c0)       = make_float2(v0, v1);
            *(float2*)(C + (size_t)(r0 + 8) * D_ + c0) = make_float2(v2, v3);
        }
    }
}

__global__ __launch_bounds__(256, 2) void gemm_qkv()
{
    if (blockIdx.z == 0)      gemm_body<2>(g_Xq,  g_Wq, g_Q);
    else if (blockIdx.z == 1) gemm_body<1>(g_Xkv, g_Wk, g_K);
    else                      gemm_body<1>(g_Xkv, g_Wv, g_V);
}

__global__ __launch_bounds__(256, 2) void gemm_out(float* __restrict__ out)
{
    gemm_body<0>(g_C, g_Wo, out);
}

// ---------------------------------------------------------------------------
// TF32 flash attention: Q fragments register-resident (R8), P relayout via
// warp shuffles (no P smem buffer) -> smem ~70KB -> 3 blocks/SM.
// Block = 64 query rows of one (b,h), 4 warps x 16 rows. K/V cp.async
// double-buffered with pre-rounded tf32 bits. Grid: (M/64, NH, B).
// ---------------------------------------------------------------------------
#define AK_STR 68
#define AV_STR 72
#define AK_OFF 0
#define AK_STAGE (64 * AK_STR)                  // 4352
#define AV_OFF (2 * AK_STAGE)                   // 8704
#define AV_STAGE (64 * AV_STR)                  // 4608
#define AMB_OFF (AV_OFF + 2 * AV_STAGE)         // 17920
#define ATT_WORDS (AMB_OFF + 64)                // 17984 words = 71936 B

#define M_INIT (-1.0e4f)
#define MASK_BIAS (-1.0e9f)

__global__ __launch_bounds__(128, 3) void attn_tc(
    const float* __restrict__ Q, const float* __restrict__ K,
    const float* __restrict__ V, float* __restrict__ Cout)
{
    extern __shared__ unsigned smemu[];
    unsigned* Kr = smemu + AK_OFF;        // tf32 bits, 2 stages
    unsigned* Vr = smemu + AV_OFF;        // tf32 bits, 2 stages
    float* mbias = (float*)(smemu + AMB_OFF);

    const int mtile = blockIdx.x, h = blockIdx.y, b = blockIdx.z;
    const int tid = threadIdx.x;
    const int warp = tid >> 5, lane = tid & 31;
    const int g = lane >> 2, t = lane & 3;
    const int mb = warp * 16;
    const int lr = tid >> 1, lch = (tid & 1) * 32;
    const unsigned srcA = (unsigned)((lane & 28) | (t >> 1));   // quad-local source
    const bool oddt = (t & 1);

    const float* Kbase = K + ((size_t)b * N_) * D_ + h * DH_;
    const float* Vbase = V + ((size_t)b * N_) * D_ + h * DH_;

    // Async preload of K/V tile 0 — overlaps the Q register loads below.
    {
        const float* ks = Kbase + (size_t)lr * D_ + lch;
        const float* vs = Vbase + (size_t)lr * D_ + lch;
        unsigned* kd = Kr + lr * AK_STR + lch;
        unsigned* vd = Vr + lr * AV_STR + lch;
#pragma unroll
        for (int i = 0; i < 8; ++i) cpasync16(kd + 4 * i, ks + 4 * i);
#pragma unroll
        for (int i = 0; i < 8; ++i) cpasync16(vd + 4 * i, vs + 4 * i);
    }
    CP_COMMIT();

    // Q a-fragments: one-time global load of pre-rounded (scaled) tf32 bits.
    unsigned qa[8][4];
    {
        const unsigned* q0 = (const unsigned*)(Q + ((size_t)(b * M_ + mtile * 64 + mb + g)) * D_ + h * DH_);
        const unsigned* q1 = (const unsigned*)(Q + ((size_t)(b * M_ + mtile * 64 + mb + g + 8)) * D_ + h * DH_);
#pragma unroll
        for (int kk = 0; kk < 8; ++kk) {
            const int kb = kk * 8;
            qa[kk][0] = q0[kb + t];
            qa[kk][1] = q1[kb + t];
            qa[kk][2] = q0[kb + t + 4];
            qa[kk][3] = q1[kb + t + 4];
        }
    }

    float m0 = M_INIT, m1 = M_INIT, l0 = 0.f, l1 = 0.f;
    float o[8][4];
#pragma unroll
    for (int i = 0; i < 8; ++i)
#pragma unroll
        for (int j = 0; j < 4; ++j) o[i][j] = 0.f;

    const int NT = N_ / 64;  // 32
    for (int kt = 0; kt < NT; ++kt) {
        const int cur = kt & 1;
        if (kt + 1 < NT) {
            const int nrow = (kt + 1) * 64 + lr;
            const float* ks = Kbase + (size_t)nrow * D_ + lch;
            const float* vs = Vbase + (size_t)nrow * D_ + lch;
            unsigned* kd = Kr + (cur ^ 1) * AK_STAGE + lr * AK_STR + lch;
            unsigned* vd = Vr + (cur ^ 1) * AV_STAGE + lr * AV_STR + lch;
#pragma unroll
            for (int i = 0; i < 8; ++i) cpasync16(kd + 4 * i, ks + 4 * i);
#pragma unroll
            for (int i = 0; i < 8; ++i) cpasync16(vd + 4 * i, vs + 4 * i);
            CP_COMMIT();
        }
        if (tid < 64)
            mbias[tid] = g_mask[b * N_ + kt * 64 + tid] ? MASK_BIAS : 0.f;
        if (kt + 1 < NT) CP_WAIT1(); else CP_WAIT0();
        __syncthreads();

        const unsigned* Kc = Kr + cur * AK_STAGE;
        const unsigned* Vc = Vr + cur * AV_STAGE;

        // S = Q K^T  (A operands in registers)
        float s[8][4];
#pragma unroll
        for (int i = 0; i < 8; ++i)
#pragma unroll
            for (int j = 0; j < 4; ++j) s[i][j] = 0.f;

#pragma unroll
        for (int kk = 0; kk < 8; ++kk) {
            const int kb = kk * 8;
#pragma unroll
            for (int nt = 0; nt < 8; ++nt) {
                unsigned b0 = Kc[(nt * 8 + g) * AK_STR + kb + t];
                unsigned b1 = Kc[(nt * 8 + g) * AK_STR + kb + t + 4];
                mma8(s[nt], qa[kk][0], qa[kk][1], qa[kk][2], qa[kk][3], b0, b1);
            }
        }

        // online softmax (base-2)
        float mx0 = -3.0e38f, mx1 = -3.0e38f;
#pragma unroll
        for (int nt = 0; nt < 8; ++nt) {
            float b0 = mbias[nt * 8 + 2 * t];
            float b1 = mbias[nt * 8 + 2 * t + 1];
            s[nt][0] += b0; s[nt][1] += b1;
            s[nt][2] += b0; s[nt][3] += b1;
            mx0 = fmaxf(mx0, fmaxf(s[nt][0], s[nt][1]));
            mx1 = fmaxf(mx1, fmaxf(s[nt][2], s[nt][3]));
        }
        mx0 = fmaxf(mx0, __shfl_xor_sync(0xFFFFFFFFu, mx0, 1));
        mx0 = fmaxf(mx0, __shfl_xor_sync(0xFFFFFFFFu, mx0, 2));
        mx1 = fmaxf(mx1, __shfl_xor_sync(0xFFFFFFFFu, mx1, 1));
        mx1 = fmaxf(mx1, __shfl_xor_sync(0xFFFFFFFFu, mx1, 2));
        float nm0 = fmaxf(m0, mx0), nm1 = fmaxf(m1, mx1);
        float cr0 = ex2(m0 - nm0), cr1 = ex2(m1 - nm1);
        m0 = nm0; m1 = nm1;

        float rs0 = 0.f, rs1 = 0.f;
#pragma unroll
        for (int nt = 0; nt < 8; ++nt) {
            s[nt][0] = ex2(s[nt][0] - nm0);
            s[nt][1] = ex2(s[nt][1] - nm0);
            s[nt][2] = ex2(s[nt][2] - nm1);
            s[nt][3] = ex2(s[nt][3] - nm1);
            rs0 += s[nt][0] + s[nt][1];
            rs1 += s[nt][2] + s[nt][3];
            o[nt][0] *= cr0; o[nt][1] *= cr0;
            o[nt][2] *= cr1; o[nt][3] *= cr1;
        }
        l0 = l0 * cr0 + rs0;
        l1 = l1 * cr1 + rs1;

        // O += P V — P a-fragments built by intra-quad shuffles (no smem).
        // a0 = P[g][kk*8+t] lives in s[kk][t&1] of lane 4g+(t>>1); the t+4
        // operands come from lane 4g+(t>>1)+2.
#pragma unroll
        for (int kk = 0; kk < 8; ++kk) {
            float v00 = __shfl_sync(0xFFFFFFFFu, s[kk][0], srcA);
            float v01 = __shfl_sync(0xFFFFFFFFu, s[kk][1], srcA);
            float v20 = __shfl_sync(0xFFFFFFFFu, s[kk][2], srcA);
            float v21 = __shfl_sync(0xFFFFFFFFu, s[kk][3], srcA);
            float w00 = __shfl_sync(0xFFFFFFFFu, s[kk][0], srcA + 2);
            float w01 = __shfl_sync(0xFFFFFFFFu, s[kk][1], srcA + 2);
            float w20 = __shfl_sync(0xFFFFFFFFu, s[kk][2], srcA + 2);
            float w21 = __shfl_sync(0xFFFFFFFFu, s[kk][3], srcA + 2);
            unsigned a0 = f2tf(oddt ? v01 : v00);
            unsigned a1 = f2tf(oddt ? v21 : v20);
            unsigned a2 = f2tf(oddt ? w01 : w00);
            unsigned a3 = f2tf(oddt ? w21 : w20);
            const int kb = kk * 8;
#pragma unroll
            for (int nt = 0; nt < 8; ++nt) {
                unsigned b0 = Vc[(kb + t) * AV_STR + nt * 8 + g];
                unsigned b1 = Vc[(kb + t + 4) * AV_STR + nt * 8 + g];
                mma8(o[nt], a0, a1, a2, a3, b0, b1);
            }
        }
        __syncthreads();   // stage fully consumed before reuse
    }

    l0 += __shfl_xor_sync(0xFFFFFFFFu, l0, 1);
    l0 += __shfl_xor_sync(0xFFFFFFFFu, l0, 2);
    l1 += __shfl_xor_sync(0xFFFFFFFFu, l1, 1);
    l1 += __shfl_xor_sync(0xFFFFFFFFu, l1, 2);
    float inv0 = 1.f / l0, inv1 = 1.f / l1;

    // Write tf32-rounded bits: the O-projection consumes them directly.
    const int gr0 = mtile * 64 + mb + g;
    const int gr1 = gr0 + 8;
#pragma unroll
    for (int nt = 0; nt < 8; ++nt) {
        int col = h * DH_ + nt * 8 + 2 * t;
        *(float2*)(Cout + ((size_t)(b * M_ + gr0)) * D_ + col) =
            make_float2(__uint_as_float(f2tf(o[nt][0] * inv0)),
                        __uint_as_float(f2tf(o[nt][1] * inv0)));
        *(float2*)(Cout + ((size_t)(b * M_ + gr1)) * D_ + col) =
            make_float2(__uint_as_float(f2tf(o[nt][2] * inv1)),
                        __uint_as_float(f2tf(o[nt][3] * inv1)));
    }
}

// ---------------------------------------------------------------------------
// Launch. Inputs: query, key_value, key_padding_mask, W_Q, W_K, W_V, W_O
// ---------------------------------------------------------------------------
extern "C" void kernel_launch(void* const* d_in, const int* in_sizes, int n_in,
                              void* d_out, int out_size)
{
    const float* query = (const float*)d_in[0];
    const float* keyv  = (const float*)d_in[1];
    const unsigned char* mask_raw = (const unsigned char*)d_in[2];
    const float* W_Q = (const float*)d_in[3];
    const float* W_K = (const float*)d_in[4];
    const float* W_V = (const float*)d_in[5];
    const float* W_O = (const float*)d_in[6];
    float* out = (float*)d_out;

    float *gQ, *gK, *gV, *gC;
    cudaGetSymbolAddress((void**)&gQ, g_Q);
    cudaGetSymbolAddress((void**)&gK, g_K);
    cudaGetSymbolAddress((void**)&gV, g_V);
    cudaGetSymbolAddress((void**)&gC, g_C);

    cudaFuncSetAttribute(attn_tc, cudaFuncAttributeMaxDynamicSharedMemorySize,
                         ATT_WORDS * 4);

    mask_expand_kernel<<<1, 1024>>>(mask_raw);

    // one-time tf32 pre-rounding of GEMM operands
    {
        const size_t total4 = (2 * NIN + 4 * NW) / 4;
        int blocks = (int)((total4 + 255) / 256);
        preround_kernel<<<blocks, 256>>>(query, keyv, W_Q, W_K, W_V, W_O);
    }

    dim3 gqkv(D_ / 128, (B_ * M_) / 128, 3);
    gemm_qkv<<<gqkv, 256>>>();

    dim3 gattn(M_ / 64, NH_, B_);
    attn_tc<<<gattn, 128, ATT_WORDS * 4>>>(gQ, gK, gV, gC);

    dim3 gout(D_ / 128, (B_ * M_) / 128);
    gemm_out<<<gout, 256>>>(out);
}

// round 10
// speedup vs baseline: 1.5465x; 1.0159x over previous
#include <cuda_runtime.h>
#include <stdint.h>

#define B_  2
#define M_  2048
#define N_  2048
#define D_  1024
#define NH_ 16
#define DH_ 64

#define NIN ((size_t)B_ * M_ * D_)   // 4M elems
#define NW  ((size_t)D_ * D_)        // 1M elems

// Scratch (device globals: no allocation allowed).
// All "float" buffers below carry tf32-rounded bit patterns unless noted.
__device__ float g_Q[NIN];           // tf32(Q*scale*log2e) bits
__device__ float g_K[NIN];           // tf32 bits
__device__ float g_V[NIN];           // tf32 bits
__device__ float g_C[NIN];           // tf32 bits (attention output)
__device__ float g_Xq[NIN];          // tf32(query) bits
__device__ float g_Xkv[NIN];         // tf32(key_value) bits
__device__ float g_Wq[NW], g_Wk[NW], g_Wv[NW], g_Wo[NW];   // tf32(weight) bits
__device__ unsigned char g_mask[B_ * N_];

// ---------------------------------------------------------------------------
// helpers
// ---------------------------------------------------------------------------
__device__ __forceinline__ unsigned f2tf(float x) {
    unsigned u; asm("cvt.rna.tf32.f32 %0, %1;" : "=r"(u) : "f"(x)); return u;
}
__device__ __forceinline__ float ex2(float x) {
    float y; asm("ex2.approx.f32 %0, %1;" : "=f"(y) : "f"(x)); return y;
}
__device__ __forceinline__ void mma8(float* c, unsigned a0, unsigned a1, unsigned a2, unsigned a3,
                                     unsigned b0, unsigned b1) {
    asm volatile(
        "mma.sync.aligned.m16n8k8.row.col.f32.tf32.tf32.f32 "
        "{%0,%1,%2,%3},{%4,%5,%6,%7},{%8,%9},{%0,%1,%2,%3};\n"
        : "+f"(c[0]), "+f"(c[1]), "+f"(c[2]), "+f"(c[3])
        : "r"(a0), "r"(a1), "r"(a2), "r"(a3), "r"(b0), "r"(b1));
}
__device__ __forceinline__ void cpasync16(void* dst, const void* src) {
    unsigned d = (unsigned)__cvta_generic_to_shared(dst);
    asm volatile("cp.async.cg.shared.global [%0], [%1], 16;\n" :: "r"(d), "l"(src));
}
#define CP_COMMIT() asm volatile("cp.async.commit_group;\n" ::: "memory")
#define CP_WAIT0()  asm volatile("cp.async.wait_group 0;\n" ::: "memory")
#define CP_WAIT1()  asm volatile("cp.async.wait_group 1;\n" ::: "memory")
#define CP_WAIT2()  asm volatile("cp.async.wait_group 2;\n" ::: "memory")

#define SCQ (0.125f * 1.44269504f)   // 1/sqrt(dh) * log2(e), folded into Q

// ---------------------------------------------------------------------------
// Mask dtype sniffer + expander (bool may arrive as u8 / i32 / f32)
// ---------------------------------------------------------------------------
__global__ void mask_expand_kernel(const unsigned char* __restrict__ raw) {
    __shared__ int s_not_int, s_not_float;
    if (threadIdx.x == 0) { s_not_int = 0; s_not_float = 0; }
    __syncthreads();
    const unsigned int* w = (const unsigned int*)raw;
    for (int i = threadIdx.x; i < 1024; i += blockDim.x) {
        unsigned int x = w[i];
        if (x != 0u && x != 1u)          atomicOr(&s_not_int, 1);
        if (x != 0u && x != 0x3F800000u) atomicOr(&s_not_float, 1);
    }
    __syncthreads();
    int mode = (!s_not_int) ? 0 : ((!s_not_float) ? 1 : 2);
    if (mode == 2) {
        for (int i = threadIdx.x; i < B_ * N_; i += blockDim.x)
            g_mask[i] = raw[i] ? 1 : 0;
    } else {
        for (int i = threadIdx.x; i < B_ * N_; i += blockDim.x)
            g_mask[i] = w[i] ? 1 : 0;
    }
}

// ---------------------------------------------------------------------------
// One-time tf32 pre-rounding of all GEMM operands (inputs + weights).
// ---------------------------------------------------------------------------
__global__ __launch_bounds__(256) void preround_kernel(
    const float* __restrict__ q, const float* __restrict__ kv,
    const float* __restrict__ wq, const float* __restrict__ wk,
    const float* __restrict__ wv, const float* __restrict__ wo)
{
    size_t i4 = (size_t)blockIdx.x * blockDim.x + threadIdx.x;
    const size_t total4 = (2 * NIN + 4 * NW) / 4;   // 3,145,728
    if (i4 >= total4) return;
    size_t off = i4 * 4;
    const float* src; float* dst;
    if (off < NIN)                       { src = q;  dst = g_Xq;  }
    else if ((off -= NIN) < NIN)         { src = kv; dst = g_Xkv; }
    else if ((off -= NIN) < NW)          { src = wq; dst = g_Wq;  }
    else if ((off -= NW) < NW)           { src = wk; dst = g_Wk;  }
    else if ((off -= NW) < NW)           { src = wv; dst = g_Wv;  }
    else         { off -= NW;              src = wo; dst = g_Wo;  }
    float4 v = *(const float4*)(src + off);
    float4 r;
    r.x = __uint_as_float(f2tf(v.x));
    r.y = __uint_as_float(f2tf(v.y));
    r.z = __uint_as_float(f2tf(v.z));
    r.w = __uint_as_float(f2tf(v.w));
    *(float4*)(dst + off) = r;
}

// ---------------------------------------------------------------------------
// TF32 GEMM (R4/R6-proven 2-stage), operands PRE-ROUNDED tf32 bits (no cvt
// in loop). 128x128 tile, BK=16, cp.async double buffer, 256 thr, (256,2).
// Epilogue MODE: 0 = plain fp32, 1 = tf32-rounded bits, 2 = tf32(acc*SCQ).
// ---------------------------------------------------------------------------
#define GA_STR 20
#define GB_STR 136
#define GA_WORDS (128 * GA_STR)
#define GB_WORDS (16 * GB_STR)

__device__ __forceinline__ void gemm_stage_load(
    const float* __restrict__ A, const float* __restrict__ Bm,
    int rowBase, int colBase, int k0, float* As, float* Bs, int tid)
{
#pragma unroll
    for (int i = 0; i < 2; ++i) {
        int f = tid + i * 256;
        int r = f >> 2, c = (f & 3) * 4;
        cpasync16(As + r * GA_STR + c, A + (size_t)(rowBase + r) * D_ + k0 + c);
    }
#pragma unroll
    for (int i = 0; i < 2; ++i) {
        int f = tid + i * 256;
        int r = f >> 5, c = (f & 31) * 4;
        cpasync16(Bs + r * GB_STR + c, Bm + (size_t)(k0 + r) * D_ + colBase + c);
    }
}

template<int MODE>
__device__ __forceinline__ void gemm_body(
    const float* __restrict__ A, const float* __restrict__ Bm, float* __restrict__ C)
{
    __shared__ float As[2][GA_WORDS];
    __shared__ float Bs[2][GB_WORDS];

    const int tid  = threadIdx.x;
    const int warp = tid >> 5, lane = tid & 31;
    const int g = lane >> 2, t = lane & 3;
    const int wm = (warp >> 2) * 64;
    const int wn = (warp & 3) * 32;
    const int rowBase = blockIdx.y * 128;
    const int colBase = blockIdx.x * 128;

    float acc[4][4][4];
#pragma unroll
    for (int i = 0; i < 4; ++i)
#pragma unroll
        for (int j = 0; j < 4; ++j)
#pragma unroll
            for (int k = 0; k < 4; ++k) acc[i][j][k] = 0.f;

    gemm_stage_load(A, Bm, rowBase, colBase, 0, As[0], Bs[0], tid);
    CP_COMMIT();

    const int NIT = D_ / 16;   // 64
    for (int it = 0; it < NIT; ++it) {
        const int cur = it & 1;
        if (it + 1 < NIT) {
            gemm_stage_load(A, Bm, rowBase, colBase, (it + 1) * 16,
                            As[cur ^ 1], Bs[cur ^ 1], tid);
            CP_COMMIT();
            CP_WAIT1();
        } else {
            CP_WAIT0();
        }
        __syncthreads();

        const unsigned* Ac = (const unsigned*)As[cur];
        const unsigned* Bc = (const unsigned*)Bs[cur];
#pragma unroll
        for (int kk = 0; kk < 2; ++kk) {
            const int kb = kk * 8;
            unsigned a[4][4], bf[4][2];
#pragma unroll
            for (int mt = 0; mt < 4; ++mt) {
                int mr = wm + mt * 16;
                a[mt][0] = Ac[(mr + g) * GA_STR + kb + t];
                a[mt][1] = Ac[(mr + g + 8) * GA_STR + kb + t];
                a[mt][2] = Ac[(mr + g) * GA_STR + kb + t + 4];
                a[mt][3] = Ac[(mr + g + 8) * GA_STR + kb + t + 4];
            }
#pragma unroll
            for (int nt = 0; nt < 4; ++nt) {
                int nc = wn + nt * 8 + g;
                bf[nt][0] = Bc[(kb + t) * GB_STR + nc];
                bf[nt][1] = Bc[(kb + t + 4) * GB_STR + nc];
            }
#pragma unroll
            for (int mt = 0; mt < 4; ++mt)
#pragma unroll
                for (int nt = 0; nt < 4; ++nt)
                    mma8(acc[mt][nt], a[mt][0], a[mt][1], a[mt][2], a[mt][3],
                         bf[nt][0], bf[nt][1]);
        }
        __syncthreads();
    }

#pragma unroll
    for (int mt = 0; mt < 4; ++mt) {
        int r0 = rowBase + wm + mt * 16 + g;
#pragma unroll
        for (int nt = 0; nt < 4; ++nt) {
            int c0 = colBase + wn + nt * 8 + 2 * t;
            float v0 = acc[mt][nt][0], v1 = acc[mt][nt][1];
            float v2 = acc[mt][nt][2], v3 = acc[mt][nt][3];
            if (MODE == 2) { v0 *= SCQ; v1 *= SCQ; v2 *= SCQ; v3 *= SCQ; }
            if (MODE != 0) {
                v0 = __uint_as_float(f2tf(v0));
                v1 = __uint_as_float(f2tf(v1));
                v2 = __uint_as_float(f2tf(v2));
                v3 = __uint_as_float(f2tf(v3));
            }
            *(float2*)(C + (size_t)r0 * D_ + c0)       = make_float2(v0, v1);
            *(float2*)(C + (size_t)(r0 + 8) * D_ + c0) = make_float2(v2, v3);
        }
    }
}

__global__ __launch_bounds__(256, 2) void gemm_qkv()
{
    if (blockIdx.z == 0)      gemm_body<2>(g_Xq,  g_Wq, g_Q);
    else if (blockIdx.z == 1) gemm_body<1>(g_Xkv, g_Wk, g_K);
    else                      gemm_body<1>(g_Xkv, g_Wv, g_V);
}

__global__ __launch_bounds__(256, 2) void gemm_out(float* __restrict__ out)
{
    gemm_body<0>(g_C, g_Wo, out);
}

// ---------------------------------------------------------------------------
// TF32 flash attention: Q fragments in registers, P relayout via shuffles,
// K double-buffered + V single-buffered cp.async (split waits) -> smem
// ~52.5KB and __launch_bounds__(128,4) -> 4 blocks/SM = 16 warps/SM.
// Block = 64 query rows of one (b,h), 4 warps x 16 rows. Grid: (M/64, NH, B).
// ---------------------------------------------------------------------------
#define AK_STR 68
#define AV_STR 72
#define AK_OFF 0
#define AK_STAGE (64 * AK_STR)                  // 4352
#define AV_OFF (2 * AK_STAGE)                   // 8704
#define AMB_OFF (AV_OFF + 64 * AV_STR)          // 13312
#define ATT_WORDS (AMB_OFF + 64)                // 13376 words = 53504 B

#define M_INIT (-1.0e4f)
#define MASK_BIAS (-1.0e9f)

__global__ __launch_bounds__(128, 4) void attn_tc(
    const float* __restrict__ Q, const float* __restrict__ K,
    const float* __restrict__ V, float* __restrict__ Cout)
{
    extern __shared__ unsigned smemu[];
    unsigned* Kr = smemu + AK_OFF;        // tf32 bits, 2 stages
    unsigned* Vr = smemu + AV_OFF;        // tf32 bits, 1 stage
    float* mbias = (float*)(smemu + AMB_OFF);

    const int mtile = blockIdx.x, h = blockIdx.y, b = blockIdx.z;
    const int tid = threadIdx.x;
    const int warp = tid >> 5, lane = tid & 31;
    const int g = lane >> 2, t = lane & 3;
    const int mb = warp * 16;
    const int lr = tid >> 1, lch = (tid & 1) * 32;
    const unsigned srcA = (unsigned)((lane & 28) | (t >> 1));   // quad-local source
    const bool oddt = (t & 1);

    const float* Kbase = K + ((size_t)b * N_) * D_ + h * DH_;
    const float* Vbase = V + ((size_t)b * N_) * D_ + h * DH_;

    // Preload: group{K0}, group{V0}
    {
        const float* ks = Kbase + (size_t)lr * D_ + lch;
        unsigned* kd = Kr + lr * AK_STR + lch;
#pragma unroll
        for (int i = 0; i < 8; ++i) cpasync16(kd + 4 * i, ks + 4 * i);
        CP_COMMIT();
        const float* vs = Vbase + (size_t)lr * D_ + lch;
        unsigned* vd = Vr + lr * AV_STR + lch;
#pragma unroll
        for (int i = 0; i < 8; ++i) cpasync16(vd + 4 * i, vs + 4 * i);
        CP_COMMIT();
    }

    // Q a-fragments: one-time global load of pre-rounded (scaled) tf32 bits.
    unsigned qa[8][4];
    {
        const unsigned* q0 = (const unsigned*)(Q + ((size_t)(b * M_ + mtile * 64 + mb + g)) * D_ + h * DH_);
        const unsigned* q1 = (const unsigned*)(Q + ((size_t)(b * M_ + mtile * 64 + mb + g + 8)) * D_ + h * DH_);
#pragma unroll
        for (int kk = 0; kk < 8; ++kk) {
            const int kb = kk * 8;
            qa[kk][0] = q0[kb + t];
            qa[kk][1] = q1[kb + t];
            qa[kk][2] = q0[kb + t + 4];
            qa[kk][3] = q1[kb + t + 4];
        }
    }

    float m0 = M_INIT, m1 = M_INIT, l0 = 0.f, l1 = 0.f;
    float o[8][4];
#pragma unroll
    for (int i = 0; i < 8; ++i)
#pragma unroll
        for (int j = 0; j < 4; ++j) o[i][j] = 0.f;

    const int NT = N_ / 64;  // 32
    for (int kt = 0; kt < NT; ++kt) {
        const int cur = kt & 1;
        // mask bias for this tile (prev iter's readers finished at its end barrier)
        if (tid < 64)
            mbias[tid] = g_mask[b * N_ + kt * 64 + tid] ? MASK_BIAS : 0.f;
        // prefetch K(kt+1) into the other stage (freed last iter)
        if (kt + 1 < NT) {
            const int nrow = (kt + 1) * 64 + lr;
            const float* ks = Kbase + (size_t)nrow * D_ + lch;
            unsigned* kd = Kr + (cur ^ 1) * AK_STAGE + lr * AK_STR + lch;
#pragma unroll
            for (int i = 0; i < 8; ++i) cpasync16(kd + 4 * i, ks + 4 * i);
            CP_COMMIT();
            CP_WAIT2();     // K(kt) + everything older complete; V(kt), K(kt+1) may fly
        } else {
            CP_WAIT1();     // only V(NT-1) may remain outstanding
        }
        __syncthreads();    // K(kt) + mbias visible

        const unsigned* Kc = Kr + cur * AK_STAGE;

        // S = Q K^T  (A operands in registers)
        float s[8][4];
#pragma unroll
        for (int i = 0; i < 8; ++i)
#pragma unroll
            for (int j = 0; j < 4; ++j) s[i][j] = 0.f;

#pragma unroll
        for (int kk = 0; kk < 8; ++kk) {
            const int kb = kk * 8;
#pragma unroll
            for (int nt = 0; nt < 8; ++nt) {
                unsigned b0 = Kc[(nt * 8 + g) * AK_STR + kb + t];
                unsigned b1 = Kc[(nt * 8 + g) * AK_STR + kb + t + 4];
                mma8(s[nt], qa[kk][0], qa[kk][1], qa[kk][2], qa[kk][3], b0, b1);
            }
        }

        // online softmax (base-2)
        float mx0 = -3.0e38f, mx1 = -3.0e38f;
#pragma unroll
        for (int nt = 0; nt < 8; ++nt) {
            float b0 = mbias[nt * 8 + 2 * t];
            float b1 = mbias[nt * 8 + 2 * t + 1];
            s[nt][0] += b0; s[nt][1] += b1;
            s[nt][2] += b0; s[nt][3] += b1;
            mx0 = fmaxf(mx0, fmaxf(s[nt][0], s[nt][1]));
            mx1 = fmaxf(mx1, fmaxf(s[nt][2], s[nt][3]));
        }
        mx0 = fmaxf(mx0, __shfl_xor_sync(0xFFFFFFFFu, mx0, 1));
        mx0 = fmaxf(mx0, __shfl_xor_sync(0xFFFFFFFFu, mx0, 2));
        mx1 = fmaxf(mx1, __shfl_xor_sync(0xFFFFFFFFu, mx1, 1));
        mx1 = fmaxf(mx1, __shfl_xor_sync(0xFFFFFFFFu, mx1, 2));
        float nm0 = fmaxf(m0, mx0), nm1 = fmaxf(m1, mx1);
        float cr0 = ex2(m0 - nm0), cr1 = ex2(m1 - nm1);
        m0 = nm0; m1 = nm1;

        float rs0 = 0.f, rs1 = 0.f;
#pragma unroll
        for (int nt = 0; nt < 8; ++nt) {
            s[nt][0] = ex2(s[nt][0] - nm0);
            s[nt][1] = ex2(s[nt][1] - nm0);
            s[nt][2] = ex2(s[nt][2] - nm1);
            s[nt][3] = ex2(s[nt][3] - nm1);
            rs0 += s[nt][0] + s[nt][1];
            rs1 += s[nt][2] + s[nt][3];
            o[nt][0] *= cr0; o[nt][1] *= cr0;
            o[nt][2] *= cr1; o[nt][3] *= cr1;
        }
        l0 = l0 * cr0 + rs0;
        l1 = l1 * cr1 + rs1;

        // V(kt) must be complete before PV (overlapped with QK+softmax above)
        if (kt + 1 < NT) CP_WAIT1(); else CP_WAIT0();
        __syncthreads();    // V(kt) visible to all warps

        // O += P V — P a-fragments built by intra-quad shuffles (no smem).
#pragma unroll
        for (int kk = 0; kk < 8; ++kk) {
            float v00 = __shfl_sync(0xFFFFFFFFu, s[kk][0], srcA);
            float v01 = __shfl_sync(0xFFFFFFFFu, s[kk][1], srcA);
            float v20 = __shfl_sync(0xFFFFFFFFu, s[kk][2], srcA);
            float v21 = __shfl_sync(0xFFFFFFFFu, s[kk][3], srcA);
            float w00 = __shfl_sync(0xFFFFFFFFu, s[kk][0], srcA + 2);
            float w01 = __shfl_sync(0xFFFFFFFFu, s[kk][1], srcA + 2);
            float w20 = __shfl_sync(0xFFFFFFFFu, s[kk][2], srcA + 2);
            float w21 = __shfl_sync(0xFFFFFFFFu, s[kk][3], srcA + 2);
            unsigned a0 = f2tf(oddt ? v01 : v00);
            unsigned a1 = f2tf(oddt ? v21 : v20);
            unsigned a2 = f2tf(oddt ? w01 : w00);
            unsigned a3 = f2tf(oddt ? w21 : w20);
            const int kb = kk * 8;
#pragma unroll
            for (int nt = 0; nt < 8; ++nt) {
                unsigned b0 = Vr[(kb + t) * AV_STR + nt * 8 + g];
                unsigned b1 = Vr[(kb + t + 4) * AV_STR + nt * 8 + g];
                mma8(o[nt], a0, a1, a2, a3, b0, b1);
            }
        }
        __syncthreads();    // all PV reads done -> V buffer free, K stage free

        // prefetch V(kt+1) into the (single) V buffer
        if (kt + 1 < NT) {
            const int nrow = (kt + 1) * 64 + lr;
            const float* vs = Vbase + (size_t)nrow * D_ + lch;
            unsigned* vd = Vr + lr * AV_STR + lch;
#pragma unroll
            for (int i = 0; i < 8; ++i) cpasync16(vd + 4 * i, vs + 4 * i);
            CP_COMMIT();
        }
    }

    l0 += __shfl_xor_sync(0xFFFFFFFFu, l0, 1);
    l0 += __shfl_xor_sync(0xFFFFFFFFu, l0, 2);
    l1 += __shfl_xor_sync(0xFFFFFFFFu, l1, 1);
    l1 += __shfl_xor_sync(0xFFFFFFFFu, l1, 2);
    float inv0 = 1.f / l0, inv1 = 1.f / l1;

    // Write tf32-rounded bits: the O-projection consumes them directly.
    const int gr0 = mtile * 64 + mb + g;
    const int gr1 = gr0 + 8;
#pragma unroll
    for (int nt = 0; nt < 8; ++nt) {
        int col = h * DH_ + nt * 8 + 2 * t;
        *(float2*)(Cout + ((size_t)(b * M_ + gr0)) * D_ + col) =
            make_float2(__uint_as_float(f2tf(o[nt][0] * inv0)),
                        __uint_as_float(f2tf(o[nt][1] * inv0)));
        *(float2*)(Cout + ((size_t)(b * M_ + gr1)) * D_ + col) =
            make_float2(__uint_as_float(f2tf(o[nt][2] * inv1)),
                        __uint_as_float(f2tf(o[nt][3] * inv1)));
    }
}

// ---------------------------------------------------------------------------
// Launch. Inputs: query, key_value, key_padding_mask, W_Q, W_K, W_V, W_O
// ---------------------------------------------------------------------------
extern "C" void kernel_launch(void* const* d_in, const int* in_sizes, int n_in,
                              void* d_out, int out_size)
{
    const float* query = (const float*)d_in[0];
    const float* keyv  = (const float*)d_in[1];
    const unsigned char* mask_raw = (const unsigned char*)d_in[2];
    const float* W_Q = (const float*)d_in[3];
    const float* W_K = (const float*)d_in[4];
    const float* W_V = (const float*)d_in[5];
    const float* W_O = (const float*)d_in[6];
    float* out = (float*)d_out;

    float *gQ, *gK, *gV, *gC;
    cudaGetSymbolAddress((void**)&gQ, g_Q);
    cudaGetSymbolAddress((void**)&gK, g_K);
    cudaGetSymbolAddress((void**)&gV, g_V);
    cudaGetSymbolAddress((void**)&gC, g_C);

    cudaFuncSetAttribute(attn_tc, cudaFuncAttributeMaxDynamicSharedMemorySize,
                         ATT_WORDS * 4);

    mask_expand_kernel<<<1, 1024>>>(mask_raw);

    // one-time tf32 pre-rounding of GEMM operands
    {
        const size_t total4 = (2 * NIN + 4 * NW) / 4;
        int blocks = (int)((total4 + 255) / 256);
        preround_kernel<<<blocks, 256>>>(query, keyv, W_Q, W_K, W_V, W_O);
    }

    dim3 gqkv(D_ / 128, (B_ * M_) / 128, 3);
    gemm_qkv<<<gqkv, 256>>>();

    dim3 gattn(M_ / 64, NH_, B_);
    attn_tc<<<gattn, 128, ATT_WORDS * 4>>>(gQ, gK, gV, gC);

    dim3 gout(D_ / 128, (B_ * M_) / 128);
    gemm_out<<<gout, 256>>>(out);
}

// round 11
// speedup vs baseline: 1.7420x; 1.1264x over previous
#include <cuda_runtime.h>
#include <stdint.h>

#define B_  2
#define M_  2048
#define N_  2048
#define D_  1024
#define NH_ 16
#define DH_ 64

#define NIN ((size_t)B_ * M_ * D_)   // 4M elems
#define NW  ((size_t)D_ * D_)        // 1M elems

// Scratch (device globals: no allocation allowed).
// All "float" buffers below carry tf32-rounded bit patterns unless noted.
__device__ float g_Q[NIN];           // tf32(Q*scale*log2e) bits
__device__ float g_K[NIN];           // tf32 bits
__device__ float g_V[NIN];           // tf32 bits
__device__ float g_C[NIN];           // tf32 bits (attention output)
__device__ float g_Xq[NIN];          // tf32(query) bits
__device__ float g_Xkv[NIN];         // tf32(key_value) bits
__device__ float g_Wq[NW], g_Wk[NW], g_Wv[NW], g_Wo[NW];   // tf32(weight) bits
__device__ unsigned char g_mask[B_ * N_];

// ---------------------------------------------------------------------------
// helpers
// ---------------------------------------------------------------------------
__device__ __forceinline__ unsigned f2tf(float x) {
    unsigned u; asm("cvt.rna.tf32.f32 %0, %1;" : "=r"(u) : "f"(x)); return u;
}
__device__ __forceinline__ float ex2(float x) {
    float y; asm("ex2.approx.f32 %0, %1;" : "=f"(y) : "f"(x)); return y;
}
__device__ __forceinline__ void mma8(float* c, unsigned a0, unsigned a1, unsigned a2, unsigned a3,
                                     unsigned b0, unsigned b1) {
    asm volatile(
        "mma.sync.aligned.m16n8k8.row.col.f32.tf32.tf32.f32 "
        "{%0,%1,%2,%3},{%4,%5,%6,%7},{%8,%9},{%0,%1,%2,%3};\n"
        : "+f"(c[0]), "+f"(c[1]), "+f"(c[2]), "+f"(c[3])
        : "r"(a0), "r"(a1), "r"(a2), "r"(a3), "r"(b0), "r"(b1));
}
__device__ __forceinline__ void cpasync16(void* dst, const void* src) {
    unsigned d = (unsigned)__cvta_generic_to_shared(dst);
    asm volatile("cp.async.cg.shared.global [%0], [%1], 16;\n" :: "r"(d), "l"(src));
}
#define CP_COMMIT() asm volatile("cp.async.commit_group;\n" ::: "memory")
#define CP_WAIT0()  asm volatile("cp.async.wait_group 0;\n" ::: "memory")
#define CP_WAIT1()  asm volatile("cp.async.wait_group 1;\n" ::: "memory")
#define CP_WAIT2()  asm volatile("cp.async.wait_group 2;\n" ::: "memory")

#define SCQ (0.125f * 1.44269504f)   // 1/sqrt(dh) * log2(e), folded into Q

// ---------------------------------------------------------------------------
// Mask dtype sniffer + expander (bool may arrive as u8 / i32 / f32)
// ---------------------------------------------------------------------------
__global__ void mask_expand_kernel(const unsigned char* __restrict__ raw) {
    __shared__ int s_not_int, s_not_float;
    if (threadIdx.x == 0) { s_not_int = 0; s_not_float = 0; }
    __syncthreads();
    const unsigned int* w = (const unsigned int*)raw;
    for (int i = threadIdx.x; i < 1024; i += blockDim.x) {
        unsigned int x = w[i];
        if (x != 0u && x != 1u)          atomicOr(&s_not_int, 1);
        if (x != 0u && x != 0x3F800000u) atomicOr(&s_not_float, 1);
    }
    __syncthreads();
    int mode = (!s_not_int) ? 0 : ((!s_not_float) ? 1 : 2);
    if (mode == 2) {
        for (int i = threadIdx.x; i < B_ * N_; i += blockDim.x)
            g_mask[i] = raw[i] ? 1 : 0;
    } else {
        for (int i = threadIdx.x; i < B_ * N_; i += blockDim.x)
            g_mask[i] = w[i] ? 1 : 0;
    }
}

// ---------------------------------------------------------------------------
// One-time tf32 pre-rounding of all GEMM operands (inputs + weights).
// ---------------------------------------------------------------------------
__global__ __launch_bounds__(256) void preround_kernel(
    const float* __restrict__ q, const float* __restrict__ kv,
    const float* __restrict__ wq, const float* __restrict__ wk,
    const float* __restrict__ wv, const float* __restrict__ wo)
{
    size_t i4 = (size_t)blockIdx.x * blockDim.x + threadIdx.x;
    const size_t total4 = (2 * NIN + 4 * NW) / 4;   // 3,145,728
    if (i4 >= total4) return;
    size_t off = i4 * 4;
    const float* src; float* dst;
    if (off < NIN)                       { src = q;  dst = g_Xq;  }
    else if ((off -= NIN) < NIN)         { src = kv; dst = g_Xkv; }
    else if ((off -= NIN) < NW)          { src = wq; dst = g_Wq;  }
    else if ((off -= NW) < NW)           { src = wk; dst = g_Wk;  }
    else if ((off -= NW) < NW)           { src = wv; dst = g_Wv;  }
    else         { off -= NW;              src = wo; dst = g_Wo;  }
    float4 v = *(const float4*)(src + off);
    float4 r;
    r.x = __uint_as_float(f2tf(v.x));
    r.y = __uint_as_float(f2tf(v.y));
    r.z = __uint_as_float(f2tf(v.z));
    r.w = __uint_as_float(f2tf(v.w));
    *(float4*)(dst + off) = r;
}

// ---------------------------------------------------------------------------
// TF32 GEMM (R4/R6-proven 2-stage), operands PRE-ROUNDED tf32 bits (no cvt
// in loop). 128x128 tile, BK=16, cp.async double buffer, 256 thr, (256,2).
// Epilogue MODE: 0 = plain fp32, 1 = tf32-rounded bits, 2 = tf32(acc*SCQ).
// ---------------------------------------------------------------------------
#define GA_STR 20
#define GB_STR 136
#define GA_WORDS (128 * GA_STR)
#define GB_WORDS (16 * GB_STR)

__device__ __forceinline__ void gemm_stage_load(
    const float* __restrict__ A, const float* __restrict__ Bm,
    int rowBase, int colBase, int k0, float* As, float* Bs, int tid)
{
#pragma unroll
    for (int i = 0; i < 2; ++i) {
        int f = tid + i * 256;
        int r = f >> 2, c = (f & 3) * 4;
        cpasync16(As + r * GA_STR + c, A + (size_t)(rowBase + r) * D_ + k0 + c);
    }
#pragma unroll
    for (int i = 0; i < 2; ++i) {
        int f = tid + i * 256;
        int r = f >> 5, c = (f & 31) * 4;
        cpasync16(Bs + r * GB_STR + c, Bm + (size_t)(k0 + r) * D_ + colBase + c);
    }
}

template<int MODE>
__device__ __forceinline__ void gemm_body(
    const float* __restrict__ A, const float* __restrict__ Bm, float* __restrict__ C)
{
    __shared__ float As[2][GA_WORDS];
    __shared__ float Bs[2][GB_WORDS];

    const int tid  = threadIdx.x;
    const int warp = tid >> 5, lane = tid & 31;
    const int g = lane >> 2, t = lane & 3;
    const int wm = (warp >> 2) * 64;
    const int wn = (warp & 3) * 32;
    const int rowBase = blockIdx.y * 128;
    const int colBase = blockIdx.x * 128;

    float acc[4][4][4];
#pragma unroll
    for (int i = 0; i < 4; ++i)
#pragma unroll
        for (int j = 0; j < 4; ++j)
#pragma unroll
            for (int k = 0; k < 4; ++k) acc[i][j][k] = 0.f;

    gemm_stage_load(A, Bm, rowBase, colBase, 0, As[0], Bs[0], tid);
    CP_COMMIT();

    const int NIT = D_ / 16;   // 64
    for (int it = 0; it < NIT; ++it) {
        const int cur = it & 1;
        if (it + 1 < NIT) {
            gemm_stage_load(A, Bm, rowBase, colBase, (it + 1) * 16,
                            As[cur ^ 1], Bs[cur ^ 1], tid);
            CP_COMMIT();
            CP_WAIT1();
        } else {
            CP_WAIT0();
        }
        __syncthreads();

        const unsigned* Ac = (const unsigned*)As[cur];
        const unsigned* Bc = (const unsigned*)Bs[cur];
#pragma unroll
        for (int kk = 0; kk < 2; ++kk) {
            const int kb = kk * 8;
            unsigned a[4][4], bf[4][2];
#pragma unroll
            for (int mt = 0; mt < 4; ++mt) {
                int mr = wm + mt * 16;
                a[mt][0] = Ac[(mr + g) * GA_STR + kb + t];
                a[mt][1] = Ac[(mr + g + 8) * GA_STR + kb + t];
                a[mt][2] = Ac[(mr + g) * GA_STR + kb + t + 4];
                a[mt][3] = Ac[(mr + g + 8) * GA_STR + kb + t + 4];
            }
#pragma unroll
            for (int nt = 0; nt < 4; ++nt) {
                int nc = wn + nt * 8 + g;
                bf[nt][0] = Bc[(kb + t) * GB_STR + nc];
                bf[nt][1] = Bc[(kb + t + 4) * GB_STR + nc];
            }
#pragma unroll
            for (int mt = 0; mt < 4; ++mt)
#pragma unroll
                for (int nt = 0; nt < 4; ++nt)
                    mma8(acc[mt][nt], a[mt][0], a[mt][1], a[mt][2], a[mt][3],
                         bf[nt][0], bf[nt][1]);
        }
        __syncthreads();
    }

#pragma unroll
    for (int mt = 0; mt < 4; ++mt) {
        int r0 = rowBase + wm + mt * 16 + g;
#pragma unroll
        for (int nt = 0; nt < 4; ++nt) {
            int c0 = colBase + wn + nt * 8 + 2 * t;
            float v0 = acc[mt][nt][0], v1 = acc[mt][nt][1];
            float v2 = acc[mt][nt][2], v3 = acc[mt][nt][3];
            if (MODE == 2) { v0 *= SCQ; v1 *= SCQ; v2 *= SCQ; v3 *= SCQ; }
            if (MODE != 0) {
                v0 = __uint_as_float(f2tf(v0));
                v1 = __uint_as_float(f2tf(v1));
                v2 = __uint_as_float(f2tf(v2));
                v3 = __uint_as_float(f2tf(v3));
            }
            *(float2*)(C + (size_t)r0 * D_ + c0)       = make_float2(v0, v1);
            *(float2*)(C + (size_t)(r0 + 8) * D_ + c0) = make_float2(v2, v3);
        }
    }
}

__global__ __launch_bounds__(256, 2) void gemm_qkv()
{
    if (blockIdx.z == 0)      gemm_body<2>(g_Xq,  g_Wq, g_Q);
    else if (blockIdx.z == 1) gemm_body<1>(g_Xkv, g_Wk, g_K);
    else                      gemm_body<1>(g_Xkv, g_Wv, g_V);
}

__global__ __launch_bounds__(256, 2) void gemm_out(float* __restrict__ out)
{
    gemm_body<0>(g_C, g_Wo, out);
}

// ---------------------------------------------------------------------------
// TF32 flash attention: TWO m16 tiles per warp (32 query rows) for chain-ILP
// and K/V b-fragment reuse (2 MMAs per LDS pair, halved L2 traffic).
// Q fragments register-resident, P relayout via shuffles, K double-buffered +
// V single-buffered cp.async. Block = 128 rows, 4 warps. Grid: (M/128, NH, B).
// __launch_bounds__(128,2): 255-reg budget, 2 blocks/SM, smem 53.5KB/block.
// ---------------------------------------------------------------------------
#define AK_STR 68
#define AV_STR 72
#define AK_OFF 0
#define AK_STAGE (64 * AK_STR)                  // 4352
#define AV_OFF (2 * AK_STAGE)                   // 8704
#define AMB_OFF (AV_OFF + 64 * AV_STR)          // 13312
#define ATT_WORDS (AMB_OFF + 64)                // 13376 words = 53504 B

#define M_INIT (-1.0e4f)
#define MASK_BIAS (-1.0e9f)

__global__ __launch_bounds__(128, 2) void attn_tc(
    const float* __restrict__ Q, const float* __restrict__ K,
    const float* __restrict__ V, float* __restrict__ Cout)
{
    extern __shared__ unsigned smemu[];
    unsigned* Kr = smemu + AK_OFF;        // tf32 bits, 2 stages
    unsigned* Vr = smemu + AV_OFF;        // tf32 bits, 1 stage
    float* mbias = (float*)(smemu + AMB_OFF);

    const int mtile = blockIdx.x, h = blockIdx.y, b = blockIdx.z;
    const int tid = threadIdx.x;
    const int warp = tid >> 5, lane = tid & 31;
    const int g = lane >> 2, t = lane & 3;
    const int mb = warp * 32;             // 32 query rows per warp
    const int lr = tid >> 1, lch = (tid & 1) * 32;
    const unsigned srcA = (unsigned)((lane & 28) | (t >> 1));   // quad-local source
    const bool oddt = (t & 1);

    const float* Kbase = K + ((size_t)b * N_) * D_ + h * DH_;
    const float* Vbase = V + ((size_t)b * N_) * D_ + h * DH_;

    // Preload: group{K0}, group{V0}
    {
        const float* ks = Kbase + (size_t)lr * D_ + lch;
        unsigned* kd = Kr + lr * AK_STR + lch;
#pragma unroll
        for (int i = 0; i < 8; ++i) cpasync16(kd + 4 * i, ks + 4 * i);
        CP_COMMIT();
        const float* vs = Vbase + (size_t)lr * D_ + lch;
        unsigned* vd = Vr + lr * AV_STR + lch;
#pragma unroll
        for (int i = 0; i < 8; ++i) cpasync16(vd + 4 * i, vs + 4 * i);
        CP_COMMIT();
    }

    // Q a-fragments for BOTH m-tiles: one-time global load of pre-rounded bits.
    unsigned qa[2][8][4];
#pragma unroll
    for (int u = 0; u < 2; ++u) {
        const unsigned* q0 = (const unsigned*)(Q + ((size_t)(b * M_ + mtile * 128 + mb + u * 16 + g)) * D_ + h * DH_);
        const unsigned* q1 = (const unsigned*)(Q + ((size_t)(b * M_ + mtile * 128 + mb + u * 16 + g + 8)) * D_ + h * DH_);
#pragma unroll
        for (int kk = 0; kk < 8; ++kk) {
            const int kb = kk * 8;
            qa[u][kk][0] = q0[kb + t];
            qa[u][kk][1] = q1[kb + t];
            qa[u][kk][2] = q0[kb + t + 4];
            qa[u][kk][3] = q1[kb + t + 4];
        }
    }

    float mS[2][2], lS[2][2];
#pragma unroll
    for (int u = 0; u < 2; ++u) { mS[u][0] = M_INIT; mS[u][1] = M_INIT; lS[u][0] = 0.f; lS[u][1] = 0.f; }
    float o[2][8][4];
#pragma unroll
    for (int u = 0; u < 2; ++u)
#pragma unroll
        for (int i = 0; i < 8; ++i)
#pragma unroll
            for (int j = 0; j < 4; ++j) o[u][i][j] = 0.f;

    const int NT = N_ / 64;  // 32
    for (int kt = 0; kt < NT; ++kt) {
        const int cur = kt & 1;
        if (tid < 64)
            mbias[tid] = g_mask[b * N_ + kt * 64 + tid] ? MASK_BIAS : 0.f;
        // prefetch K(kt+1)
        if (kt + 1 < NT) {
            const int nrow = (kt + 1) * 64 + lr;
            const float* ks = Kbase + (size_t)nrow * D_ + lch;
            unsigned* kd = Kr + (cur ^ 1) * AK_STAGE + lr * AK_STR + lch;
#pragma unroll
            for (int i = 0; i < 8; ++i) cpasync16(kd + 4 * i, ks + 4 * i);
            CP_COMMIT();
            CP_WAIT2();     // K(kt) complete; V(kt), K(kt+1) may fly
        } else {
            CP_WAIT1();     // only V(NT-1) may remain outstanding
        }
        __syncthreads();    // K(kt) + mbias visible

        const unsigned* Kc = Kr + cur * AK_STAGE;

        // S = Q K^T for both m-tiles — each K fragment pair feeds 2 MMAs
        float s[2][8][4];
#pragma unroll
        for (int u = 0; u < 2; ++u)
#pragma unroll
            for (int i = 0; i < 8; ++i)
#pragma unroll
                for (int j = 0; j < 4; ++j) s[u][i][j] = 0.f;

#pragma unroll
        for (int kk = 0; kk < 8; ++kk) {
            const int kb = kk * 8;
#pragma unroll
            for (int nt = 0; nt < 8; ++nt) {
                unsigned b0 = Kc[(nt * 8 + g) * AK_STR + kb + t];
                unsigned b1 = Kc[(nt * 8 + g) * AK_STR + kb + t + 4];
                mma8(s[0][nt], qa[0][kk][0], qa[0][kk][1], qa[0][kk][2], qa[0][kk][3], b0, b1);
                mma8(s[1][nt], qa[1][kk][0], qa[1][kk][1], qa[1][kk][2], qa[1][kk][3], b0, b1);
            }
        }

        // online softmax (base-2), independent per m-tile (ILP)
#pragma unroll
        for (int u = 0; u < 2; ++u) {
            float mx0 = -3.0e38f, mx1 = -3.0e38f;
#pragma unroll
            for (int nt = 0; nt < 8; ++nt) {
                float b0 = mbias[nt * 8 + 2 * t];
                float b1 = mbias[nt * 8 + 2 * t + 1];
                s[u][nt][0] += b0; s[u][nt][1] += b1;
                s[u][nt][2] += b0; s[u][nt][3] += b1;
                mx0 = fmaxf(mx0, fmaxf(s[u][nt][0], s[u][nt][1]));
                mx1 = fmaxf(mx1, fmaxf(s[u][nt][2], s[u][nt][3]));
            }
            mx0 = fmaxf(mx0, __shfl_xor_sync(0xFFFFFFFFu, mx0, 1));
            mx0 = fmaxf(mx0, __shfl_xor_sync(0xFFFFFFFFu, mx0, 2));
            mx1 = fmaxf(mx1, __shfl_xor_sync(0xFFFFFFFFu, mx1, 1));
            mx1 = fmaxf(mx1, __shfl_xor_sync(0xFFFFFFFFu, mx1, 2));
            float nm0 = fmaxf(mS[u][0], mx0), nm1 = fmaxf(mS[u][1], mx1);
            float cr0 = ex2(mS[u][0] - nm0), cr1 = ex2(mS[u][1] - nm1);
            mS[u][0] = nm0; mS[u][1] = nm1;

            float rs0 = 0.f, rs1 = 0.f;
#pragma unroll
            for (int nt = 0; nt < 8; ++nt) {
                s[u][nt][0] = ex2(s[u][nt][0] - nm0);
                s[u][nt][1] = ex2(s[u][nt][1] - nm0);
                s[u][nt][2] = ex2(s[u][nt][2] - nm1);
                s[u][nt][3] = ex2(s[u][nt][3] - nm1);
                rs0 += s[u][nt][0] + s[u][nt][1];
                rs1 += s[u][nt][2] + s[u][nt][3];
                o[u][nt][0] *= cr0; o[u][nt][1] *= cr0;
                o[u][nt][2] *= cr1; o[u][nt][3] *= cr1;
            }
            lS[u][0] = lS[u][0] * cr0 + rs0;
            lS[u][1] = lS[u][1] * cr1 + rs1;
        }

        // V(kt) must be complete before PV (overlapped with QK+softmax above)
        if (kt + 1 < NT) CP_WAIT1(); else CP_WAIT0();
        __syncthreads();    // V(kt) visible to all warps

        // O += P V — P a-fragments via intra-quad shuffles; each V fragment
        // pair feeds 2 MMAs (one per m-tile).
#pragma unroll
        for (int kk = 0; kk < 8; ++kk) {
            unsigned a[2][4];
#pragma unroll
            for (int u = 0; u < 2; ++u) {
                float v00 = __shfl_sync(0xFFFFFFFFu, s[u][kk][0], srcA);
                float v01 = __shfl_sync(0xFFFFFFFFu, s[u][kk][1], srcA);
                float v20 = __shfl_sync(0xFFFFFFFFu, s[u][kk][2], srcA);
                float v21 = __shfl_sync(0xFFFFFFFFu, s[u][kk][3], srcA);
                float w00 = __shfl_sync(0xFFFFFFFFu, s[u][kk][0], srcA + 2);
                float w01 = __shfl_sync(0xFFFFFFFFu, s[u][kk][1], srcA + 2);
                float w20 = __shfl_sync(0xFFFFFFFFu, s[u][kk][2], srcA + 2);
                float w21 = __shfl_sync(0xFFFFFFFFu, s[u][kk][3], srcA + 2);
                a[u][0] = f2tf(oddt ? v01 : v00);
                a[u][1] = f2tf(oddt ? v21 : v20);
                a[u][2] = f2tf(oddt ? w01 : w00);
                a[u][3] = f2tf(oddt ? w21 : w20);
            }
            const int kb = kk * 8;
#pragma unroll
            for (int nt = 0; nt < 8; ++nt) {
                unsigned b0 = Vr[(kb + t) * AV_STR + nt * 8 + g];
                unsigned b1 = Vr[(kb + t + 4) * AV_STR + nt * 8 + g];
                mma8(o[0][nt], a[0][0], a[0][1], a[0][2], a[0][3], b0, b1);
                mma8(o[1][nt], a[1][0], a[1][1], a[1][2], a[1][3], b0, b1);
            }
        }
        __syncthreads();    // all PV reads done -> V buffer free, K stage free

        // prefetch V(kt+1) into the (single) V buffer
        if (kt + 1 < NT) {
            const int nrow = (kt + 1) * 64 + lr;
            const float* vs = Vbase + (size_t)nrow * D_ + lch;
            unsigned* vd = Vr + lr * AV_STR + lch;
#pragma unroll
            for (int i = 0; i < 8; ++i) cpasync16(vd + 4 * i, vs + 4 * i);
            CP_COMMIT();
        }
    }

    // finalize both m-tiles
#pragma unroll
    for (int u = 0; u < 2; ++u) {
        float l0 = lS[u][0], l1 = lS[u][1];
        l0 += __shfl_xor_sync(0xFFFFFFFFu, l0, 1);
        l0 += __shfl_xor_sync(0xFFFFFFFFu, l0, 2);
        l1 += __shfl_xor_sync(0xFFFFFFFFu, l1, 1);
        l1 += __shfl_xor_sync(0xFFFFFFFFu, l1, 2);
        float inv0 = 1.f / l0, inv1 = 1.f / l1;

        const int gr0 = mtile * 128 + mb + u * 16 + g;
        const int gr1 = gr0 + 8;
#pragma unroll
        for (int nt = 0; nt < 8; ++nt) {
            int col = h * DH_ + nt * 8 + 2 * t;
            *(float2*)(Cout + ((size_t)(b * M_ + gr0)) * D_ + col) =
                make_float2(__uint_as_float(f2tf(o[u][nt][0] * inv0)),
                            __uint_as_float(f2tf(o[u][nt][1] * inv0)));
            *(float2*)(Cout + ((size_t)(b * M_ + gr1)) * D_ + col) =
                make_float2(__uint_as_float(f2tf(o[u][nt][2] * inv1)),
                            __uint_as_float(f2tf(o[u][nt][3] * inv1)));
        }
    }
}

// ---------------------------------------------------------------------------
// Launch. Inputs: query, key_value, key_padding_mask, W_Q, W_K, W_V, W_O
// ---------------------------------------------------------------------------
extern "C" void kernel_launch(void* const* d_in, const int* in_sizes, int n_in,
                              void* d_out, int out_size)
{
    const float* query = (const float*)d_in[0];
    const float* keyv  = (const float*)d_in[1];
    const unsigned char* mask_raw = (const unsigned char*)d_in[2];
    const float* W_Q = (const float*)d_in[3];
    const float* W_K = (const float*)d_in[4];
    const float* W_V = (const float*)d_in[5];
    const float* W_O = (const float*)d_in[6];
    float* out = (float*)d_out;

    float *gQ, *gK, *gV, *gC;
    cudaGetSymbolAddress((void**)&gQ, g_Q);
    cudaGetSymbolAddress((void**)&gK, g_K);
    cudaGetSymbolAddress((void**)&gV, g_V);
    cudaGetSymbolAddress((void**)&gC, g_C);

    cudaFuncSetAttribute(attn_tc, cudaFuncAttributeMaxDynamicSharedMemorySize,
                         ATT_WORDS * 4);

    mask_expand_kernel<<<1, 1024>>>(mask_raw);

    // one-time tf32 pre-rounding of GEMM operands
    {
        const size_t total4 = (2 * NIN + 4 * NW) / 4;
        int blocks = (int)((total4 + 255) / 256);
        preround_kernel<<<blocks, 256>>>(query, keyv, W_Q, W_K, W_V, W_O);
    }

    dim3 gqkv(D_ / 128, (B_ * M_) / 128, 3);
    gemm_qkv<<<gqkv, 256>>>();

    dim3 gattn(M_ / 128, NH_, B_);
    attn_tc<<<gattn, 128, ATT_WORDS * 4>>>(gQ, gK, gV, gC);

    dim3 gout(D_ / 128, (B_ * M_) / 128);
    gemm_out<<<gout, 256>>>(out);
}